// round 2
// baseline (speedup 1.0000x reference)
#include <cuda_runtime.h>
#include <math.h>

#define B_    16
#define N_    8192
#define D_    384
#define DEG_  16
#define K_    8
#define H_    128
#define NODES (B_ * N_)        // 131072
#define WCOLS 256              // fused [W1_top | P1_top] output width

// ---------------- device scratch (no allocs allowed) ----------------
__device__ float g_Wtop[D_ * WCOLS];     // 384x256 fused top weights
__device__ float g_qc[B_ * WCOLS];       // per-batch q @ W_bot + bias
__device__ float g_amps[NODES * K_];     // amps [B,N,K]
__device__ float g_bufA[NODES * K_];
__device__ float g_bufB[NODES * K_];
__device__ float g_absum[NODES];
__device__ float g_part[512];            // per-block sumsq partials
__device__ float g_sumsq[B_];

// ---------------- prep: fuse top weights ----------------
__global__ void prep_wtop(const float* __restrict__ W1, const float* __restrict__ P1) {
    int i = blockIdx.x * blockDim.x + threadIdx.x;   // exactly 384*256 threads
    int d = i >> 8;
    int h = i & 255;
    g_Wtop[i] = (h < H_) ? W1[d * H_ + h] : P1[d * H_ + (h - H_)];
}

// ---------------- prep: per-batch q @ W_bot + bias ----------------
__global__ void prep_qc(const float* __restrict__ q,
                        const float* __restrict__ W1, const float* __restrict__ b1,
                        const float* __restrict__ P1, const float* __restrict__ pb1) {
    __shared__ float qs[D_];
    int b = blockIdx.x;
    int j = threadIdx.x;            // 0..255
    for (int d = j; d < D_; d += 256) qs[d] = q[b * D_ + d];
    __syncthreads();
    float s;
    const float* w;
    if (j < H_) { s = b1[j];       w = W1 + (size_t)D_ * H_ + j; }
    else        { s = pb1[j - H_]; w = P1 + (size_t)D_ * H_ + (j - H_); }
#pragma unroll 4
    for (int d = 0; d < D_; d++) s = fmaf(qs[d], w[(size_t)d * H_], s);
    g_qc[b * WCOLS + j] = s;
}

// ---------------- main fused GEMM + MLP epilogue ----------------
// C[131072,256] = emb @ g_Wtop, tile 64 rows x 256 cols per block,
// epilogue: relu(+qc) -> layer2 (warp shuffle reduce) -> amps * (1+path)
__global__ __launch_bounds__(256, 2)
void gemm_kernel(const float* __restrict__ emb, const int* __restrict__ labels,
                 const float* __restrict__ W2, const float* __restrict__ b2,
                 const float* __restrict__ P2, const float* __restrict__ pb2) {
    __shared__ __align__(16) float As[8][68];     // pad 68: conflict-free STS/LDS
    __shared__ __align__(16) float Bs[8][WCOLS];
    __shared__ __align__(16) float qcs[WCOLS];
    __shared__ float b2s[K_];
    __shared__ float pb2s;

    const int tid = threadIdx.x;
    const int tx = tid & 31;        // col group
    const int ty = tid >> 5;        // row group (same for whole warp)
    const int row0 = blockIdx.x * 64;
    const int b = row0 >> 13;

    qcs[tid] = g_qc[b * WCOLS + tid];
    if (tid < K_) b2s[tid] = b2[tid];
    if (tid == 0) pb2s = pb2[0];

    float acc[8][8];
#pragma unroll
    for (int i = 0; i < 8; i++)
#pragma unroll
        for (int j = 0; j < 8; j++) acc[i][j] = 0.f;

    const int ar = tid >> 3;        // 0..31
    const int ak = tid & 7;
    const float* aptr  = emb + (size_t)(row0 + ar) * D_ + ak;
    const float* aptr2 = aptr + (size_t)32 * D_;

    for (int k0 = 0; k0 < D_; k0 += 8) {
        __syncthreads();
        As[ak][ar]      = aptr[k0];
        As[ak][ar + 32] = aptr2[k0];
        const float* wp = g_Wtop + k0 * WCOLS + tid;
#pragma unroll
        for (int j = 0; j < 8; j++) Bs[j][tid] = wp[j * WCOLS];
        __syncthreads();
#pragma unroll
        for (int kk = 0; kk < 8; kk++) {
            float4 a0 = *(const float4*)&As[kk][ty * 8];
            float4 a1 = *(const float4*)&As[kk][ty * 8 + 4];
            float4 b0 = *(const float4*)&Bs[kk][tx * 4];
            float4 b1 = *(const float4*)&Bs[kk][128 + tx * 4];
            float av[8] = {a0.x, a0.y, a0.z, a0.w, a1.x, a1.y, a1.z, a1.w};
            float bv[8] = {b0.x, b0.y, b0.z, b0.w, b1.x, b1.y, b1.z, b1.w};
#pragma unroll
            for (int i = 0; i < 8; i++)
#pragma unroll
                for (int j = 0; j < 8; j++)
                    acc[i][j] = fmaf(av[i], bv[j], acc[i][j]);
        }
    }

    // ---- epilogue: thread's h cols = tx*4+i, p cols = 128+tx*4+i ----
    float w2r[4][8], p2r[4];
#pragma unroll
    for (int i = 0; i < 4; i++) {
        int c = tx * 4 + i;
        p2r[i] = __ldg(&P2[c]);
#pragma unroll
        for (int k = 0; k < 8; k++) w2r[i][k] = __ldg(&W2[c * 8 + k]);
    }
    float4 hq = *(const float4*)&qcs[tx * 4];
    float4 pq = *(const float4*)&qcs[128 + tx * 4];
    const float hqa[4] = {hq.x, hq.y, hq.z, hq.w};
    const float pqa[4] = {pq.x, pq.y, pq.z, pq.w};
    const float pb2v = pb2s;

#pragma unroll
    for (int ri = 0; ri < 8; ri++) {
        float part[9];
#pragma unroll
        for (int k = 0; k < 9; k++) part[k] = 0.f;
#pragma unroll
        for (int i = 0; i < 4; i++) {
            float h = fmaxf(acc[ri][i] + hqa[i], 0.f);
            float p = fmaxf(acc[ri][4 + i] + pqa[i], 0.f);
#pragma unroll
            for (int k = 0; k < 8; k++) part[k] = fmaf(h, w2r[i][k], part[k]);
            part[8] = fmaf(p, p2r[i], part[8]);
        }
#pragma unroll
        for (int off = 16; off > 0; off >>= 1)
#pragma unroll
            for (int k = 0; k < 9; k++)
                part[k] += __shfl_xor_sync(0xffffffffu, part[k], off);

        int row = row0 + ty * 8 + ri;
        float logit = part[8] + pb2v;
        float path = 1.f / (1.f + expf(-logit)) + (float)labels[row];
        float factor = 1.f + path;
        if (tx < K_) {
            float amp = 0.f;    // select part[tx] without dynamic reg indexing
#pragma unroll
            for (int k = 0; k < 8; k++)
                if (tx == k) amp = part[k];
            g_amps[(size_t)row * K_ + tx] = (amp + b2s[tx]) * factor;
        }
    }
}

// ---------------- diffusion ----------------
__device__ __forceinline__ void gather16(const float4* __restrict__ base,
                                         const int4* __restrict__ nb,
                                         float4& s0, float4& s1) {
    s0 = make_float4(0.f, 0.f, 0.f, 0.f);
    s1 = make_float4(0.f, 0.f, 0.f, 0.f);
#pragma unroll
    for (int j = 0; j < 4; j++) {
        int4 id = nb[j];
        const float4* p;
        float4 v;
        p = base + (size_t)id.x * 2;
        v = p[0]; s0.x += v.x; s0.y += v.y; s0.z += v.z; s0.w += v.w;
        v = p[1]; s1.x += v.x; s1.y += v.y; s1.z += v.z; s1.w += v.w;
        p = base + (size_t)id.y * 2;
        v = p[0]; s0.x += v.x; s0.y += v.y; s0.z += v.z; s0.w += v.w;
        v = p[1]; s1.x += v.x; s1.y += v.y; s1.z += v.z; s1.w += v.w;
        p = base + (size_t)id.z * 2;
        v = p[0]; s0.x += v.x; s0.y += v.y; s0.z += v.z; s0.w += v.w;
        v = p[1]; s1.x += v.x; s1.y += v.y; s1.z += v.z; s1.w += v.w;
        p = base + (size_t)id.w * 2;
        v = p[0]; s0.x += v.x; s0.y += v.y; s0.z += v.z; s0.w += v.w;
        v = p[1]; s1.x += v.x; s1.y += v.y; s1.z += v.z; s1.w += v.w;
    }
}

__device__ __forceinline__ void spmm_body(const float* __restrict__ in,
                                          float* __restrict__ out,
                                          const int* __restrict__ neighbors) {
    int node = blockIdx.x * blockDim.x + threadIdx.x;
    int b = node >> 13;
    const int4* nb = (const int4*)(neighbors + (size_t)node * DEG_);
    const float4* base = (const float4*)(in + (size_t)b * N_ * K_);
    float4 s0, s1;
    gather16(base, nb, s0, s1);
    const float4* am = (const float4*)(g_amps + (size_t)node * K_);
    float4 a0 = am[0], a1 = am[1];
    float4* o = (float4*)(out + (size_t)node * K_);
    o[0] = make_float4(s0.x * a0.x, s0.y * a0.y, s0.z * a0.z, s0.w * a0.w);
    o[1] = make_float4(s1.x * a1.x, s1.y * a1.y, s1.z * a1.z, s1.w * a1.w);
}

__global__ void spmm_step1(const int* __restrict__ neighbors) { spmm_body(g_amps, g_bufA, neighbors); }
__global__ void spmm_step2(const int* __restrict__ neighbors) { spmm_body(g_bufA, g_bufB, neighbors); }

__global__ void spmm_final(const int* __restrict__ neighbors) {
    int node = blockIdx.x * blockDim.x + threadIdx.x;
    int b = node >> 13;
    const int4* nb = (const int4*)(neighbors + (size_t)node * DEG_);
    const float4* base = (const float4*)(g_bufB + (size_t)b * N_ * K_);
    float4 s0, s1;
    gather16(base, nb, s0, s1);
    float absum = fabsf(s0.x) + fabsf(s0.y) + fabsf(s0.z) + fabsf(s0.w)
                + fabsf(s1.x) + fabsf(s1.y) + fabsf(s1.z) + fabsf(s1.w);
    float ss = s0.x * s0.x + s0.y * s0.y + s0.z * s0.z + s0.w * s0.w
             + s1.x * s1.x + s1.y * s1.y + s1.z * s1.z + s1.w * s1.w;
    g_absum[node] = absum;

    __shared__ float red[256];
    int t = threadIdx.x;
    red[t] = ss;
    __syncthreads();
#pragma unroll
    for (int s = 128; s > 0; s >>= 1) {
        if (t < s) red[t] += red[t + s];
        __syncthreads();
    }
    if (t == 0) g_part[blockIdx.x] = red[0];   // deterministic: no atomics
}

__global__ void reduce_sumsq() {
    int b = threadIdx.x;
    if (b < B_) {
        float s = 0.f;
        for (int i = 0; i < 32; i++) s += g_part[b * 32 + i];  // 32 blocks/batch
        g_sumsq[b] = s;
    }
}

__global__ void finalize(float* __restrict__ out) {
    int node = blockIdx.x * blockDim.x + threadIdx.x;
    int b = node >> 13;
    float ss = g_sumsq[b];
    float scale = (ss > 0.f) ? rsqrtf(ss) : 1.f;
    out[node] = g_absum[node] * scale;
}

// ---------------- launch ----------------
extern "C" void kernel_launch(void* const* d_in, const int* in_sizes, int n_in,
                              void* d_out, int out_size) {
    const float* q_embs    = (const float*)d_in[0];
    const float* emb       = (const float*)d_in[1];
    const int*   neighbors = (const int*)d_in[2];
    const int*   labels    = (const int*)d_in[3];
    const float* W1        = (const float*)d_in[4];
    const float* b1        = (const float*)d_in[5];
    const float* W2        = (const float*)d_in[6];
    const float* b2        = (const float*)d_in[7];
    const float* P1        = (const float*)d_in[8];
    const float* pb1       = (const float*)d_in[9];
    const float* P2        = (const float*)d_in[10];
    const float* pb2       = (const float*)d_in[11];
    float* out = (float*)d_out;

    prep_wtop<<<(D_ * WCOLS) / 1024, 1024>>>(W1, P1);
    prep_qc<<<B_, 256>>>(q_embs, W1, b1, P1, pb1);
    gemm_kernel<<<NODES / 64, 256>>>(emb, labels, W2, b2, P2, pb2);
    spmm_step1<<<NODES / 256, 256>>>(neighbors);
    spmm_step2<<<NODES / 256, 256>>>(neighbors);
    spmm_final<<<NODES / 256, 256>>>(neighbors);
    reduce_sumsq<<<1, 32>>>();
    finalize<<<NODES / 256, 256>>>(out);
}

// round 5
// speedup vs baseline: 1.7966x; 1.7966x over previous
#include <cuda_runtime.h>
#include <cuda_bf16.h>
#include <math.h>
#include <stdint.h>

#define B_    16
#define N_    8192
#define D_    384
#define DEG_  16
#define K_    8
#define H_    128
#define NODES (B_ * N_)
#define WCOLS 256
#define MTILE 128
#define KCH   64
#define NCH   (D_ / KCH)

// ---- smem layout (bytes) ----
#define SM_QC     0          // 256 f32
#define SM_W2     1024       // 128x8 f32
#define SM_P2     5120       // 128 f32
#define SM_B2     5632       // 8 f32
#define SM_PB2    5664       // 1 f32
#define SM_AHI    6144       // 128x64 bf16 = 16KB
#define SM_ALO    22528      // 16KB
#define SM_BBUF   38912      // 2 x (Bhi 32KB + Blo 32KB) = 128KB
#define SM_TOTAL  169984
// epilogue reuse (after mainloop):
#define SM_EPART  6144       // 8 x 128 x 12 f32 = 48KB
#define SM_FIN    55296      // 128 x 12 f32

__device__ float g_qc[B_ * WCOLS];
__device__ __nv_bfloat16 g_WhiT[WCOLS * D_];   // BT[n][k] row-major (k contiguous)
__device__ __nv_bfloat16 g_WloT[WCOLS * D_];
__device__ float g_W2[H_ * K_];
__device__ float g_P2[H_];
__device__ float g_b2[K_];
__device__ float g_pb2[1];
__device__ float g_amps[NODES * K_];
__device__ float g_bufA[NODES * K_];
__device__ float g_bufB[NODES * K_];
__device__ float g_absum[NODES];
__device__ float g_part[512];
__device__ float g_sumsq[B_];

// ---------------- helpers ----------------
__device__ __forceinline__ uint32_t smem_u32(const void* p) {
    uint32_t a;
    asm("{ .reg .u64 t; cvta.to.shared.u64 t, %1; cvt.u32.u64 %0, t; }" : "=r"(a) : "l"(p));
    return a;
}
__device__ __forceinline__ uint32_t pk2(__nv_bfloat16 a, __nv_bfloat16 b) {
    __nv_bfloat162 t(a, b);
    return *reinterpret_cast<uint32_t*>(&t);
}
// XOR swizzle: 16B-granule rotate within 128B row by (row&7)
__device__ __forceinline__ uint32_t swz(int row, int kbyte) {
    return (uint32_t)(row * 128 + (kbyte ^ ((row & 7) << 4)));
}
__device__ __forceinline__ void cp16(uint32_t dst, const void* src) {
    asm volatile("cp.async.cg.shared.global [%0], [%1], 16;" :: "r"(dst), "l"(src) : "memory");
}
__device__ __forceinline__ void cp_commit() {
    asm volatile("cp.async.commit_group;" ::: "memory");
}
__device__ __forceinline__ void mma_bf16(float* d, const uint32_t* a, const uint32_t* b) {
    asm volatile(
        "mma.sync.aligned.m16n8k16.row.col.f32.bf16.bf16.f32 "
        "{%0,%1,%2,%3}, {%4,%5,%6,%7}, {%8,%9}, {%0,%1,%2,%3};"
        : "+f"(d[0]), "+f"(d[1]), "+f"(d[2]), "+f"(d[3])
        : "r"(a[0]), "r"(a[1]), "r"(a[2]), "r"(a[3]), "r"(b[0]), "r"(b[1]));
}

// ---------------- prep kernels ----------------
__global__ void prep_wt(const float* __restrict__ W1, const float* __restrict__ P1) {
    int i = blockIdx.x * blockDim.x + threadIdx.x;   // 256*384
    int n = i / D_;
    int kd = i - n * D_;
    float v = (n < H_) ? W1[kd * H_ + n] : P1[kd * H_ + (n - H_)];
    __nv_bfloat16 hi = __float2bfloat16(v);
    __nv_bfloat16 lo = __float2bfloat16(v - __bfloat162float(hi));
    g_WhiT[i] = hi;
    g_WloT[i] = lo;
}

__global__ void prep_qc(const float* __restrict__ q,
                        const float* __restrict__ W1, const float* __restrict__ b1,
                        const float* __restrict__ P1, const float* __restrict__ pb1) {
    __shared__ float qs[D_];
    int b = blockIdx.x;
    int j = threadIdx.x;
    for (int d = j; d < D_; d += 256) qs[d] = q[b * D_ + d];
    __syncthreads();
    float s;
    const float* w;
    if (j < H_) { s = b1[j];       w = W1 + (size_t)D_ * H_ + j; }
    else        { s = pb1[j - H_]; w = P1 + (size_t)D_ * H_ + (j - H_); }
#pragma unroll 4
    for (int d = 0; d < D_; d++) s = fmaf(qs[d], w[(size_t)d * H_], s);
    g_qc[b * WCOLS + j] = s;
}

__global__ void prep_small(const float* __restrict__ W2, const float* __restrict__ b2,
                           const float* __restrict__ P2, const float* __restrict__ pb2) {
    int i = threadIdx.x;
    if (i < H_ * K_) g_W2[i] = W2[i];
    if (i < H_) g_P2[i] = P2[i];
    if (i < K_) g_b2[i] = b2[i];
    if (i == 0) g_pb2[0] = pb2[0];
}

// ---------------- GEMM: 128x256 tile / CTA, 512 threads, 16 warps ----------------
// warp (wm, wn): wm = wid>>3 (64-row band), wn = wid&7 (32-col slice).
// 3-pass bf16 split: Ahi*Bhi + Ahi*Blo + Alo*Bhi, fp32 accum.
__global__ __launch_bounds__(512, 1)
void gemm_tc(const float* __restrict__ emb, const int* __restrict__ labels) {
    extern __shared__ char smem[];
    const uint32_t sb = smem_u32(smem);
    const int tid = threadIdx.x;
    const int wid = tid >> 5;
    const int lane = tid & 31;
    const int row0 = blockIdx.x * MTILE;
    const int b = row0 >> 13;

    // tables
    if (tid < WCOLS) ((float*)(smem + SM_QC))[tid] = g_qc[b * WCOLS + tid];
    if (tid < H_ * K_ / 2) {
        ((float*)(smem + SM_W2))[tid * 2]     = g_W2[tid * 2];
        ((float*)(smem + SM_W2))[tid * 2 + 1] = g_W2[tid * 2 + 1];
    }
    if (tid < H_) ((float*)(smem + SM_P2))[tid] = g_P2[tid];
    if (tid < K_) ((float*)(smem + SM_B2))[tid] = g_b2[tid];
    if (tid == 0) *((float*)(smem + SM_PB2)) = g_pb2[0];

    // ---- B chunk prefetch via cp.async (L2-hot weights, already bf16 hi/lo) ----
    // thread covers 4 granules of Bhi + 4 of Blo per chunk: idx = tid*4+i,
    // n = idx>>3, g = idx&7
    auto issueB = [&](int c, int buf) {
        uint32_t bhi = sb + SM_BBUF + buf * 65536;
        uint32_t blo = bhi + 32768;
#pragma unroll
        for (int i = 0; i < 4; i++) {
            int idx = tid * 4 + i;
            int n = idx >> 3, g = idx & 7;
            uint32_t off = swz(n, g * 16);
            const char* sh = (const char*)(g_WhiT + (size_t)n * D_ + c * KCH) + g * 16;
            const char* sl = (const char*)(g_WloT + (size_t)n * D_ + c * KCH) + g * 16;
            cp16(bhi + off, sh);
            cp16(blo + off, sl);
        }
        cp_commit();
    };

    issueB(0, 0);
    issueB(1, 1);

    // A prefetch regs (chunk 0): thread -> row r = tid>>2, quarter q = tid&3 (16 floats)
    const int ar = tid >> 2;
    const int aq = tid & 3;
    const float* abase = emb + (size_t)(row0 + ar) * D_ + aq * 16;
    float4 pv0 = *(const float4*)(abase + 0);
    float4 pv1 = *(const float4*)(abase + 4);
    float4 pv2 = *(const float4*)(abase + 8);
    float4 pv3 = *(const float4*)(abase + 12);

    // accumulators: [mf][nf][j]
    float acc[4][4][4];
#pragma unroll
    for (int i = 0; i < 4; i++)
#pragma unroll
        for (int j = 0; j < 4; j++)
#pragma unroll
            for (int k = 0; k < 4; k++) acc[i][j][k] = 0.f;

    const int wm = wid >> 3;
    const int wn = wid & 7;
    const int m0 = wm * 64;
    const int n0 = wn * 32;
    const int g4 = lane >> 2;       // group id
    const int t4 = lane & 3;

    for (int c = 0; c < NCH; c++) {
        const int buf = c & 1;
        // ensure B(c) resident (B(c+1) may still be in flight)
        if (c == NCH - 1) asm volatile("cp.async.wait_group 0;" ::: "memory");
        else              asm volatile("cp.async.wait_group 1;" ::: "memory");

        // convert prefetched A -> bf16 hi/lo, swizzled STS
        {
            __nv_bfloat16 h[16], l[16];
            const float* pv = &pv0.x;     // pv0..pv3 contiguous in regs
            float vv[16] = {pv0.x, pv0.y, pv0.z, pv0.w, pv1.x, pv1.y, pv1.z, pv1.w,
                            pv2.x, pv2.y, pv2.z, pv2.w, pv3.x, pv3.y, pv3.z, pv3.w};
            (void)pv;
#pragma unroll
            for (int i = 0; i < 16; i++) {
                h[i] = __float2bfloat16(vv[i]);
                l[i] = __float2bfloat16(vv[i] - __bfloat162float(h[i]));
            }
            uint32_t o0 = swz(ar, aq * 32);
            uint32_t o1 = swz(ar, aq * 32 + 16);
            uint32_t hi0[4] = {pk2(h[0], h[1]), pk2(h[2], h[3]), pk2(h[4], h[5]), pk2(h[6], h[7])};
            uint32_t hi1[4] = {pk2(h[8], h[9]), pk2(h[10], h[11]), pk2(h[12], h[13]), pk2(h[14], h[15])};
            uint32_t lo0[4] = {pk2(l[0], l[1]), pk2(l[2], l[3]), pk2(l[4], l[5]), pk2(l[6], l[7])};
            uint32_t lo1[4] = {pk2(l[8], l[9]), pk2(l[10], l[11]), pk2(l[12], l[13]), pk2(l[14], l[15])};
            *(uint4*)(smem + SM_AHI + o0) = make_uint4(hi0[0], hi0[1], hi0[2], hi0[3]);
            *(uint4*)(smem + SM_AHI + o1) = make_uint4(hi1[0], hi1[1], hi1[2], hi1[3]);
            *(uint4*)(smem + SM_ALO + o0) = make_uint4(lo0[0], lo0[1], lo0[2], lo0[3]);
            *(uint4*)(smem + SM_ALO + o1) = make_uint4(lo1[0], lo1[1], lo1[2], lo1[3]);
        }
        __syncthreads();

        // prefetch next A chunk
        if (c + 1 < NCH) {
            const float* nb = abase + (c + 1) * KCH;
            pv0 = *(const float4*)(nb + 0);
            pv1 = *(const float4*)(nb + 4);
            pv2 = *(const float4*)(nb + 8);
            pv3 = *(const float4*)(nb + 12);
        }

        const char* Ahi = smem + SM_AHI;
        const char* Alo = smem + SM_ALO;
        const char* Bhi = smem + SM_BBUF + buf * 65536;
        const char* Blo = Bhi + 32768;

#pragma unroll
        for (int ks = 0; ks < 4; ks++) {
            uint32_t af[4][4], bh[4][2], bl[4][2];
            const int kb = ks * 32 + t4 * 4;
            // A hi frags
#pragma unroll
            for (int mf = 0; mf < 4; mf++) {
                int r = m0 + mf * 16 + g4;
                af[mf][0] = *(const uint32_t*)(Ahi + swz(r,      kb));
                af[mf][1] = *(const uint32_t*)(Ahi + swz(r + 8,  kb));
                af[mf][2] = *(const uint32_t*)(Ahi + swz(r,      kb + 16));
                af[mf][3] = *(const uint32_t*)(Ahi + swz(r + 8,  kb + 16));
            }
            // B hi frags
#pragma unroll
            for (int nf = 0; nf < 4; nf++) {
                int n = n0 + nf * 8 + g4;
                bh[nf][0] = *(const uint32_t*)(Bhi + swz(n, kb));
                bh[nf][1] = *(const uint32_t*)(Bhi + swz(n, kb + 16));
            }
#pragma unroll
            for (int mf = 0; mf < 4; mf++)
#pragma unroll
                for (int nf = 0; nf < 4; nf++)
                    mma_bf16(acc[mf][nf], af[mf], bh[nf]);
            // B lo frags, Ahi x Blo
#pragma unroll
            for (int nf = 0; nf < 4; nf++) {
                int n = n0 + nf * 8 + g4;
                bl[nf][0] = *(const uint32_t*)(Blo + swz(n, kb));
                bl[nf][1] = *(const uint32_t*)(Blo + swz(n, kb + 16));
            }
#pragma unroll
            for (int mf = 0; mf < 4; mf++)
#pragma unroll
                for (int nf = 0; nf < 4; nf++)
                    mma_bf16(acc[mf][nf], af[mf], bl[nf]);
            // A lo frags (reuse regs), Alo x Bhi
#pragma unroll
            for (int mf = 0; mf < 4; mf++) {
                int r = m0 + mf * 16 + g4;
                af[mf][0] = *(const uint32_t*)(Alo + swz(r,      kb));
                af[mf][1] = *(const uint32_t*)(Alo + swz(r + 8,  kb));
                af[mf][2] = *(const uint32_t*)(Alo + swz(r,      kb + 16));
                af[mf][3] = *(const uint32_t*)(Alo + swz(r + 8,  kb + 16));
            }
#pragma unroll
            for (int mf = 0; mf < 4; mf++)
#pragma unroll
                for (int nf = 0; nf < 4; nf++)
                    mma_bf16(acc[mf][nf], af[mf], bh[nf]);
        }
        __syncthreads();    // A smem + B buf free

        if (c + 2 < NCH) issueB(c + 2, buf);
    }

    // ---------------- epilogue ----------------
    const float* qcs = (const float*)(smem + SM_QC);
    const float* W2s = (const float*)(smem + SM_W2);
    const float* P2s = (const float*)(smem + SM_P2);
    float* epart = (float*)(smem + SM_EPART);
    const bool hiddenw = (wn < 4);

#pragma unroll
    for (int mf = 0; mf < 4; mf++) {
#pragma unroll
        for (int rg = 0; rg < 2; rg++) {
            int row = m0 + mf * 16 + g4 + rg * 8;
            float p[9] = {0.f, 0.f, 0.f, 0.f, 0.f, 0.f, 0.f, 0.f, 0.f};
#pragma unroll
            for (int nf = 0; nf < 4; nf++) {
#pragma unroll
                for (int cp = 0; cp < 2; cp++) {
                    int col = n0 + nf * 8 + t4 * 2 + cp;
                    float hv = fmaxf(acc[mf][nf][rg * 2 + cp] + qcs[col], 0.f);
                    if (hiddenw) {
                        const float* w = W2s + col * 8;
#pragma unroll
                        for (int k = 0; k < 8; k++) p[k] = fmaf(hv, w[k], p[k]);
                    } else {
                        p[8] = fmaf(hv, P2s[col - 128], p[8]);
                    }
                }
            }
#pragma unroll
            for (int k = 0; k < 9; k++) {
                p[k] += __shfl_xor_sync(0xffffffffu, p[k], 1);
                p[k] += __shfl_xor_sync(0xffffffffu, p[k], 2);
            }
            if (t4 == 0) {
                float* e = epart + ((size_t)wn * 128 + row) * 12;
                if (hiddenw) {
#pragma unroll
                    for (int k = 0; k < 8; k++) e[k] = p[k];
                } else {
                    e[8] = p[8];
                }
            }
        }
    }
    __syncthreads();

    float* fin = (float*)(smem + SM_FIN);
    for (int t = tid; t < 128 * 9; t += 512) {
        int row = t / 9, k = t - row * 9;
        float s;
        if (k < 8)
            s = epart[(0 * 128 + row) * 12 + k] + epart[(1 * 128 + row) * 12 + k]
              + epart[(2 * 128 + row) * 12 + k] + epart[(3 * 128 + row) * 12 + k];
        else
            s = epart[(4 * 128 + row) * 12 + 8] + epart[(5 * 128 + row) * 12 + 8]
              + epart[(6 * 128 + row) * 12 + 8] + epart[(7 * 128 + row) * 12 + 8];
        fin[row * 12 + k] = s;
    }
    __syncthreads();

    if (tid < 128) {
        int row = row0 + tid;
        float logit = fin[tid * 12 + 8] + *((const float*)(smem + SM_PB2));
        float path = 1.f / (1.f + expf(-logit)) + (float)labels[row];
        float factor = 1.f + path;
        const float* b2s = (const float*)(smem + SM_B2);
        float4 o0 = make_float4((fin[tid * 12 + 0] + b2s[0]) * factor,
                                (fin[tid * 12 + 1] + b2s[1]) * factor,
                                (fin[tid * 12 + 2] + b2s[2]) * factor,
                                (fin[tid * 12 + 3] + b2s[3]) * factor);
        float4 o1 = make_float4((fin[tid * 12 + 4] + b2s[4]) * factor,
                                (fin[tid * 12 + 5] + b2s[5]) * factor,
                                (fin[tid * 12 + 6] + b2s[6]) * factor,
                                (fin[tid * 12 + 7] + b2s[7]) * factor);
        *(float4*)(g_amps + (size_t)row * K_)     = o0;
        *(float4*)(g_amps + (size_t)row * K_ + 4) = o1;
    }
}

// ---------------- diffusion (unchanged, L2-resident) ----------------
__device__ __forceinline__ void gather16(const float4* __restrict__ base,
                                         const int4* __restrict__ nb,
                                         float4& s0, float4& s1) {
    s0 = make_float4(0.f, 0.f, 0.f, 0.f);
    s1 = make_float4(0.f, 0.f, 0.f, 0.f);
#pragma unroll
    for (int j = 0; j < 4; j++) {
        int4 id = nb[j];
        const float4* p;
        float4 v;
        p = base + (size_t)id.x * 2;
        v = p[0]; s0.x += v.x; s0.y += v.y; s0.z += v.z; s0.w += v.w;
        v = p[1]; s1.x += v.x; s1.y += v.y; s1.z += v.z; s1.w += v.w;
        p = base + (size_t)id.y * 2;
        v = p[0]; s0.x += v.x; s0.y += v.y; s0.z += v.z; s0.w += v.w;
        v = p[1]; s1.x += v.x; s1.y += v.y; s1.z += v.z; s1.w += v.w;
        p = base + (size_t)id.z * 2;
        v = p[0]; s0.x += v.x; s0.y += v.y; s0.z += v.z; s0.w += v.w;
        v = p[1]; s1.x += v.x; s1.y += v.y; s1.z += v.z; s1.w += v.w;
        p = base + (size_t)id.w * 2;
        v = p[0]; s0.x += v.x; s0.y += v.y; s0.z += v.z; s0.w += v.w;
        v = p[1]; s1.x += v.x; s1.y += v.y; s1.z += v.z; s1.w += v.w;
    }
}

__device__ __forceinline__ void spmm_body(const float* __restrict__ in,
                                          float* __restrict__ out,
                                          const int* __restrict__ neighbors) {
    int node = blockIdx.x * blockDim.x + threadIdx.x;
    int b = node >> 13;
    const int4* nb = (const int4*)(neighbors + (size_t)node * DEG_);
    const float4* base = (const float4*)(in + (size_t)b * N_ * K_);
    float4 s0, s1;
    gather16(base, nb, s0, s1);
    const float4* am = (const float4*)(g_amps + (size_t)node * K_);
    float4 a0 = am[0], a1 = am[1];
    float4* o = (float4*)(out + (size_t)node * K_);
    o[0] = make_float4(s0.x * a0.x, s0.y * a0.y, s0.z * a0.z, s0.w * a0.w);
    o[1] = make_float4(s1.x * a1.x, s1.y * a1.y, s1.z * a1.z, s1.w * a1.w);
}

__global__ void spmm_step1(const int* __restrict__ neighbors) { spmm_body(g_amps, g_bufA, neighbors); }
__global__ void spmm_step2(const int* __restrict__ neighbors) { spmm_body(g_bufA, g_bufB, neighbors); }

__global__ void spmm_final(const int* __restrict__ neighbors) {
    int node = blockIdx.x * blockDim.x + threadIdx.x;
    int b = node >> 13;
    const int4* nb = (const int4*)(neighbors + (size_t)node * DEG_);
    const float4* base = (const float4*)(g_bufB + (size_t)b * N_ * K_);
    float4 s0, s1;
    gather16(base, nb, s0, s1);
    float absum = fabsf(s0.x) + fabsf(s0.y) + fabsf(s0.z) + fabsf(s0.w)
                + fabsf(s1.x) + fabsf(s1.y) + fabsf(s1.z) + fabsf(s1.w);
    float ss = s0.x * s0.x + s0.y * s0.y + s0.z * s0.z + s0.w * s0.w
             + s1.x * s1.x + s1.y * s1.y + s1.z * s1.z + s1.w * s1.w;
    g_absum[node] = absum;

    __shared__ float red[256];
    int t = threadIdx.x;
    red[t] = ss;
    __syncthreads();
#pragma unroll
    for (int s = 128; s > 0; s >>= 1) {
        if (t < s) red[t] += red[t + s];
        __syncthreads();
    }
    if (t == 0) g_part[blockIdx.x] = red[0];
}

__global__ void reduce_sumsq() {
    int b = threadIdx.x;
    if (b < B_) {
        float s = 0.f;
        for (int i = 0; i < 32; i++) s += g_part[b * 32 + i];
        g_sumsq[b] = s;
    }
}

__global__ void finalize(float* __restrict__ out) {
    int node = blockIdx.x * blockDim.x + threadIdx.x;
    int b = node >> 13;
    float ss = g_sumsq[b];
    float scale = (ss > 0.f) ? rsqrtf(ss) : 1.f;
    out[node] = g_absum[node] * scale;
}

// ---------------- launch ----------------
extern "C" void kernel_launch(void* const* d_in, const int* in_sizes, int n_in,
                              void* d_out, int out_size) {
    const float* q_embs    = (const float*)d_in[0];
    const float* emb       = (const float*)d_in[1];
    const int*   neighbors = (const int*)d_in[2];
    const int*   labels    = (const int*)d_in[3];
    const float* W1        = (const float*)d_in[4];
    const float* b1        = (const float*)d_in[5];
    const float* W2        = (const float*)d_in[6];
    const float* b2        = (const float*)d_in[7];
    const float* P1        = (const float*)d_in[8];
    const float* pb1       = (const float*)d_in[9];
    const float* P2        = (const float*)d_in[10];
    const float* pb2       = (const float*)d_in[11];
    float* out = (float*)d_out;

    cudaFuncSetAttribute(gemm_tc, cudaFuncAttributeMaxDynamicSharedMemorySize, SM_TOTAL);

    prep_wt<<<(WCOLS * D_) / 256, 256>>>(W1, P1);
    prep_qc<<<B_, 256>>>(q_embs, W1, b1, P1, pb1);
    prep_small<<<1, 1024>>>(W2, b2, P2, pb2);
    gemm_tc<<<NODES / MTILE, 512, SM_TOTAL>>>(emb, labels);
    spmm_step1<<<NODES / 256, 256>>>(neighbors);
    spmm_step2<<<NODES / 256, 256>>>(neighbors);
    spmm_final<<<NODES / 256, 256>>>(neighbors);
    reduce_sumsq<<<1, 32>>>();
    finalize<<<NODES / 256, 256>>>(out);
}

// round 7
// speedup vs baseline: 1.9045x; 1.0600x over previous
#include <cuda_runtime.h>
#include <cuda_bf16.h>
#include <math.h>
#include <stdint.h>

#define B_    16
#define N_    8192
#define D_    384
#define DEG_  16
#define K_    8
#define H_    128
#define NODES (B_ * N_)
#define WCOLS 256
#define MTILE 128
#define KCH   64
#define NCH   (D_ / KCH)

// ---- smem layout (bytes) ----
#define SM_QC     0          // 256 f32
#define SM_W2     1024       // 128x8 f32
#define SM_P2     5120       // 128 f32
#define SM_B2     5632       // 8 f32
#define SM_PB2    5664       // 1 f32
#define SM_A      6144       // 2 bufs x (hi 16KB + lo 16KB) = 64KB
#define SM_B      71680      // 2 bufs x (hi 32KB + lo 32KB) = 128KB
#define SM_TOTAL  202752
// epilogue reuse (inside A region, after mainloop):
#define SM_EPART  6144       // 8 x 128 x 12 f32 = 48KB
#define SM_FIN    55296      // 128 x 12 f32

__device__ float g_qc[B_ * WCOLS];
__device__ __nv_bfloat16 g_WhiT[WCOLS * D_];   // BT[n][k], k contiguous
__device__ __nv_bfloat16 g_WloT[WCOLS * D_];
__device__ float g_W2[H_ * K_];
__device__ float g_P2[H_];
__device__ float g_b2[K_];
__device__ float g_pb2[1];
__device__ float g_amps[NODES * K_];
__device__ float g_bufA[NODES * K_];
__device__ float g_bufB[NODES * K_];
__device__ float g_absum[NODES];
__device__ float g_part[512];
__device__ float g_sumsq[B_];

// ---------------- helpers ----------------
__device__ __forceinline__ uint32_t smem_u32(const void* p) {
    uint32_t a;
    asm("{ .reg .u64 t; cvta.to.shared.u64 t, %1; cvt.u32.u64 %0, t; }" : "=r"(a) : "l"(p));
    return a;
}
__device__ __forceinline__ uint32_t pk2(__nv_bfloat16 a, __nv_bfloat16 b) {
    __nv_bfloat162 t(a, b);
    return *reinterpret_cast<uint32_t*>(&t);
}
// XOR swizzle: 16B-granule rotate within 128B row by (row&7)
__device__ __forceinline__ uint32_t swz(int row, int kbyte) {
    return (uint32_t)(row * 128 + (kbyte ^ ((row & 7) << 4)));
}
__device__ __forceinline__ void cp16(uint32_t dst, const void* src) {
    asm volatile("cp.async.cg.shared.global [%0], [%1], 16;" :: "r"(dst), "l"(src) : "memory");
}
__device__ __forceinline__ void cp_commit() {
    asm volatile("cp.async.commit_group;" ::: "memory");
}
__device__ __forceinline__ void mma_bf16(float* d, const uint32_t* a, const uint32_t* b) {
    asm volatile(
        "mma.sync.aligned.m16n8k16.row.col.f32.bf16.bf16.f32 "
        "{%0,%1,%2,%3}, {%4,%5,%6,%7}, {%8,%9}, {%0,%1,%2,%3};"
        : "+f"(d[0]), "+f"(d[1]), "+f"(d[2]), "+f"(d[3])
        : "r"(a[0]), "r"(a[1]), "r"(a[2]), "r"(a[3]), "r"(b[0]), "r"(b[1]));
}
__device__ __forceinline__ void ldm_x4(uint32_t& r0, uint32_t& r1, uint32_t& r2, uint32_t& r3,
                                       uint32_t addr) {
    asm volatile("ldmatrix.sync.aligned.m8n8.x4.shared.b16 {%0,%1,%2,%3}, [%4];"
                 : "=r"(r0), "=r"(r1), "=r"(r2), "=r"(r3) : "r"(addr));
}

// ---------------- prep kernels ----------------
__global__ void prep_wt(const float* __restrict__ W1, const float* __restrict__ P1) {
    int i = blockIdx.x * blockDim.x + threadIdx.x;   // 256*384
    int n = i / D_;
    int kd = i - n * D_;
    float v = (n < H_) ? W1[kd * H_ + n] : P1[kd * H_ + (n - H_)];
    __nv_bfloat16 hi = __float2bfloat16(v);
    __nv_bfloat16 lo = __float2bfloat16(v - __bfloat162float(hi));
    g_WhiT[i] = hi;
    g_WloT[i] = lo;
}

__global__ void prep_qc(const float* __restrict__ q,
                        const float* __restrict__ W1, const float* __restrict__ b1,
                        const float* __restrict__ P1, const float* __restrict__ pb1) {
    __shared__ float qs[D_];
    int b = blockIdx.x;
    int j = threadIdx.x;
    for (int d = j; d < D_; d += 256) qs[d] = q[b * D_ + d];
    __syncthreads();
    float s;
    const float* w;
    if (j < H_) { s = b1[j];       w = W1 + (size_t)D_ * H_ + j; }
    else        { s = pb1[j - H_]; w = P1 + (size_t)D_ * H_ + (j - H_); }
#pragma unroll 4
    for (int d = 0; d < D_; d++) s = fmaf(qs[d], w[(size_t)d * H_], s);
    g_qc[b * WCOLS + j] = s;
}

__global__ void prep_small(const float* __restrict__ W2, const float* __restrict__ b2,
                           const float* __restrict__ P2, const float* __restrict__ pb2) {
    int i = threadIdx.x;
    if (i < H_ * K_) g_W2[i] = W2[i];
    if (i < H_) g_P2[i] = P2[i];
    if (i < K_) g_b2[i] = b2[i];
    if (i == 0) g_pb2[0] = pb2[0];
}

// ---------------- GEMM: 128x256 tile / CTA, 512 threads, 16 warps ----------------
__global__ __launch_bounds__(512, 1)
void gemm_tc(const float* __restrict__ emb, const int* __restrict__ labels) {
    extern __shared__ char smem[];
    const uint32_t sb = smem_u32(smem);
    const int tid = threadIdx.x;
    const int wid = tid >> 5;
    const int lane = tid & 31;
    const int row0 = blockIdx.x * MTILE;
    const int b = row0 >> 13;

    // tables
    if (tid < WCOLS) ((float*)(smem + SM_QC))[tid] = g_qc[b * WCOLS + tid];
    if (tid < H_ * K_ / 2) {
        ((float*)(smem + SM_W2))[tid * 2]     = g_W2[tid * 2];
        ((float*)(smem + SM_W2))[tid * 2 + 1] = g_W2[tid * 2 + 1];
    }
    if (tid < H_) ((float*)(smem + SM_P2))[tid] = g_P2[tid];
    if (tid < K_) ((float*)(smem + SM_B2))[tid] = g_b2[tid];
    if (tid == 0) *((float*)(smem + SM_PB2)) = g_pb2[0];

    // ---- B chunk prefetch via cp.async ----
    auto issueB = [&](int c, int buf) {
        uint32_t bhi = sb + SM_B + buf * 65536;
        uint32_t blo = bhi + 32768;
#pragma unroll
        for (int i = 0; i < 4; i++) {
            int idx = tid * 4 + i;
            int n = idx >> 3, g = idx & 7;
            uint32_t off = swz(n, g * 16);
            const char* sh = (const char*)(g_WhiT + (size_t)n * D_ + c * KCH) + g * 16;
            const char* sl = (const char*)(g_WloT + (size_t)n * D_ + c * KCH) + g * 16;
            cp16(bhi + off, sh);
            cp16(blo + off, sl);
        }
        cp_commit();
    };

    issueB(0, 0);
    issueB(1, 1);

    // A staging: thread -> row ar = tid>>2, 16 floats at quarter aq
    const int ar = tid >> 2;
    const int aq = tid & 3;
    const float* abase = emb + (size_t)(row0 + ar) * D_ + aq * 16;

    auto stsA = [&](const float4& v0, const float4& v1, const float4& v2, const float4& v3,
                    int buf) {
        uint32_t ahi = sb + SM_A + buf * 32768;
        uint32_t alo = ahi + 16384;
        float vv[16] = {v0.x, v0.y, v0.z, v0.w, v1.x, v1.y, v1.z, v1.w,
                        v2.x, v2.y, v2.z, v2.w, v3.x, v3.y, v3.z, v3.w};
        __nv_bfloat16 h[16], l[16];
#pragma unroll
        for (int i = 0; i < 16; i++) {
            h[i] = __float2bfloat16(vv[i]);
            l[i] = __float2bfloat16(vv[i] - __bfloat162float(h[i]));
        }
        uint32_t o0 = swz(ar, aq * 32);
        uint32_t o1 = swz(ar, aq * 32 + 16);
        asm volatile("st.shared.v4.b32 [%0], {%1,%2,%3,%4};" :: "r"(ahi + o0),
                     "r"(pk2(h[0], h[1])), "r"(pk2(h[2], h[3])),
                     "r"(pk2(h[4], h[5])), "r"(pk2(h[6], h[7])) : "memory");
        asm volatile("st.shared.v4.b32 [%0], {%1,%2,%3,%4};" :: "r"(ahi + o1),
                     "r"(pk2(h[8], h[9])), "r"(pk2(h[10], h[11])),
                     "r"(pk2(h[12], h[13])), "r"(pk2(h[14], h[15])) : "memory");
        asm volatile("st.shared.v4.b32 [%0], {%1,%2,%3,%4};" :: "r"(alo + o0),
                     "r"(pk2(l[0], l[1])), "r"(pk2(l[2], l[3])),
                     "r"(pk2(l[4], l[5])), "r"(pk2(l[6], l[7])) : "memory");
        asm volatile("st.shared.v4.b32 [%0], {%1,%2,%3,%4};" :: "r"(alo + o1),
                     "r"(pk2(l[8], l[9])), "r"(pk2(l[10], l[11])),
                     "r"(pk2(l[12], l[13])), "r"(pk2(l[14], l[15])) : "memory");
    };

    // prologue: A(0) -> buf0; A(1) held in regs
    float4 pv0 = *(const float4*)(abase + 0);
    float4 pv1 = *(const float4*)(abase + 4);
    float4 pv2 = *(const float4*)(abase + 8);
    float4 pv3 = *(const float4*)(abase + 12);
    stsA(pv0, pv1, pv2, pv3, 0);
    pv0 = *(const float4*)(abase + KCH + 0);
    pv1 = *(const float4*)(abase + KCH + 4);
    pv2 = *(const float4*)(abase + KCH + 8);
    pv3 = *(const float4*)(abase + KCH + 12);

    // accumulators
    float acc[4][4][4];
#pragma unroll
    for (int i = 0; i < 4; i++)
#pragma unroll
        for (int j = 0; j < 4; j++)
#pragma unroll
            for (int k = 0; k < 4; k++) acc[i][j][k] = 0.f;

    const int wm = wid >> 3;
    const int wn = wid & 7;
    const int m0 = wm * 64;
    const int n0 = wn * 32;
    const int g4 = lane >> 2;
    const int t4 = lane & 3;

    // ---- per-lane ldmatrix address constants ----
    // A x4 tile (16x16): lanes 0-7 -> (m+lr, k), 8-15 -> (m+8+lr, k), 16-23 -> (m+lr, k+16B),
    // 24-31 -> (m+8+lr, k+16B)
    const int lr = lane & 7;
    const int sel = lane >> 3;
    const uint32_t xorm = (uint32_t)(lr << 4);
    const uint32_t koffA = (sel & 2) ? 16u : 0u;
    uint32_t aRow[4];
#pragma unroll
    for (int mf = 0; mf < 4; mf++)
        aRow[mf] = (uint32_t)((m0 + mf * 16 + lr + ((sel & 1) ? 8 : 0)) * 128);
    // B x4 pair (two n8k16 frags): lanes 0-7 -> (n+lr, k), 8-15 -> (n+lr, k+16B),
    // 16-23 -> (n+8+lr, k), 24-31 -> (n+8+lr, k+16B)
    const uint32_t koffB = (sel & 1) ? 16u : 0u;
    uint32_t bRow[2];
#pragma unroll
    for (int nfp = 0; nfp < 2; nfp++)
        bRow[nfp] = (uint32_t)((n0 + nfp * 16 + ((sel >> 1) ? 8 : 0) + lr) * 128);

    for (int c = 0; c < NCH; c++) {
        const int buf = c & 1;
        if (c == NCH - 1) asm volatile("cp.async.wait_group 0;" ::: "memory");
        else              asm volatile("cp.async.wait_group 1;" ::: "memory");

        // convert+store A(c+1) into other buffer (no conflict with mma's reads)
        if (c + 1 < NCH) stsA(pv0, pv1, pv2, pv3, (c + 1) & 1);
        __syncthreads();        // B(c) visible to all; A(c) visible from prev iter

        const uint32_t AhiB = sb + SM_A + buf * 32768;
        const uint32_t AloB = AhiB + 16384;
        const uint32_t BhiB = sb + SM_B + buf * 65536;
        const uint32_t BloB = BhiB + 32768;

#pragma unroll
        for (int ks = 0; ks < 4; ks++) {
            const uint32_t koff = (uint32_t)(ks * 32);
            uint32_t ah[4][4], bh[4][2], bl[4][2];
            const uint32_t aoff = (koff + koffA) ^ xorm;
            const uint32_t boff = (koff + koffB) ^ xorm;
#pragma unroll
            for (int nfp = 0; nfp < 2; nfp++)
                ldm_x4(bh[nfp * 2][0], bh[nfp * 2][1], bh[nfp * 2 + 1][0], bh[nfp * 2 + 1][1],
                       BhiB + bRow[nfp] + boff);
#pragma unroll
            for (int mf = 0; mf < 4; mf++)
                ldm_x4(ah[mf][0], ah[mf][1], ah[mf][2], ah[mf][3], AhiB + aRow[mf] + aoff);
#pragma unroll
            for (int mf = 0; mf < 4; mf++)
#pragma unroll
                for (int nf = 0; nf < 4; nf++)
                    mma_bf16(acc[mf][nf], ah[mf], bh[nf]);
#pragma unroll
            for (int nfp = 0; nfp < 2; nfp++)
                ldm_x4(bl[nfp * 2][0], bl[nfp * 2][1], bl[nfp * 2 + 1][0], bl[nfp * 2 + 1][1],
                       BloB + bRow[nfp] + boff);
#pragma unroll
            for (int mf = 0; mf < 4; mf++)
#pragma unroll
                for (int nf = 0; nf < 4; nf++)
                    mma_bf16(acc[mf][nf], ah[mf], bl[nf]);
#pragma unroll
            for (int mf = 0; mf < 4; mf++)
                ldm_x4(ah[mf][0], ah[mf][1], ah[mf][2], ah[mf][3], AloB + aRow[mf] + aoff);
#pragma unroll
            for (int mf = 0; mf < 4; mf++)
#pragma unroll
                for (int nf = 0; nf < 4; nf++)
                    mma_bf16(acc[mf][nf], ah[mf], bh[nf]);
        }
        __syncthreads();        // Bbuf[buf] free for c+2; Abuf[(c+1)&1] published

        if (c + 2 < NCH) {
            issueB(c + 2, buf);
            const float* nb = abase + (c + 2) * KCH;
            pv0 = *(const float4*)(nb + 0);
            pv1 = *(const float4*)(nb + 4);
            pv2 = *(const float4*)(nb + 8);
            pv3 = *(const float4*)(nb + 12);
        }
    }

    // ---------------- epilogue ----------------
    const float* qcs = (const float*)(smem + SM_QC);
    const float* W2s = (const float*)(smem + SM_W2);
    const float* P2s = (const float*)(smem + SM_P2);
    float* epart = (float*)(smem + SM_EPART);
    const bool hiddenw = (wn < 4);

#pragma unroll
    for (int mf = 0; mf < 4; mf++) {
#pragma unroll
        for (int rg = 0; rg < 2; rg++) {
            int row = m0 + mf * 16 + g4 + rg * 8;
            float p[9] = {0.f, 0.f, 0.f, 0.f, 0.f, 0.f, 0.f, 0.f, 0.f};
#pragma unroll
            for (int nf = 0; nf < 4; nf++) {
#pragma unroll
                for (int cp = 0; cp < 2; cp++) {
                    int col = n0 + nf * 8 + t4 * 2 + cp;
                    float hv = fmaxf(acc[mf][nf][rg * 2 + cp] + qcs[col], 0.f);
                    if (hiddenw) {
                        const float* w = W2s + col * 8;
#pragma unroll
                        for (int k = 0; k < 8; k++) p[k] = fmaf(hv, w[k], p[k]);
                    } else {
                        p[8] = fmaf(hv, P2s[col - 128], p[8]);
                    }
                }
            }
#pragma unroll
            for (int k = 0; k < 9; k++) {
                p[k] += __shfl_xor_sync(0xffffffffu, p[k], 1);
                p[k] += __shfl_xor_sync(0xffffffffu, p[k], 2);
            }
            if (t4 == 0) {
                float* e = epart + ((size_t)wn * 128 + row) * 12;
                if (hiddenw) {
#pragma unroll
                    for (int k = 0; k < 8; k++) e[k] = p[k];
                } else {
                    e[8] = p[8];
                }
            }
        }
    }
    __syncthreads();

    float* fin = (float*)(smem + SM_FIN);
    for (int t = tid; t < 128 * 9; t += 512) {
        int row = t / 9, k = t - row * 9;
        float s;
        if (k < 8)
            s = epart[(0 * 128 + row) * 12 + k] + epart[(1 * 128 + row) * 12 + k]
              + epart[(2 * 128 + row) * 12 + k] + epart[(3 * 128 + row) * 12 + k];
        else
            s = epart[(4 * 128 + row) * 12 + 8] + epart[(5 * 128 + row) * 12 + 8]
              + epart[(6 * 128 + row) * 12 + 8] + epart[(7 * 128 + row) * 12 + 8];
        fin[row * 12 + k] = s;
    }
    __syncthreads();

    if (tid < 128) {
        int row = row0 + tid;
        float logit = fin[tid * 12 + 8] + *((const float*)(smem + SM_PB2));
        float path = 1.f / (1.f + expf(-logit)) + (float)labels[row];
        float factor = 1.f + path;
        const float* b2s = (const float*)(smem + SM_B2);
        float4 o0 = make_float4((fin[tid * 12 + 0] + b2s[0]) * factor,
                                (fin[tid * 12 + 1] + b2s[1]) * factor,
                                (fin[tid * 12 + 2] + b2s[2]) * factor,
                                (fin[tid * 12 + 3] + b2s[3]) * factor);
        float4 o1 = make_float4((fin[tid * 12 + 4] + b2s[4]) * factor,
                                (fin[tid * 12 + 5] + b2s[5]) * factor,
                                (fin[tid * 12 + 6] + b2s[6]) * factor,
                                (fin[tid * 12 + 7] + b2s[7]) * factor);
        *(float4*)(g_amps + (size_t)row * K_)     = o0;
        *(float4*)(g_amps + (size_t)row * K_ + 4) = o1;
    }
}

// ---------------- diffusion (unchanged, L2-resident) ----------------
__device__ __forceinline__ void gather16(const float4* __restrict__ base,
                                         const int4* __restrict__ nb,
                                         float4& s0, float4& s1) {
    s0 = make_float4(0.f, 0.f, 0.f, 0.f);
    s1 = make_float4(0.f, 0.f, 0.f, 0.f);
#pragma unroll
    for (int j = 0; j < 4; j++) {
        int4 id = nb[j];
        const float4* p;
        float4 v;
        p = base + (size_t)id.x * 2;
        v = p[0]; s0.x += v.x; s0.y += v.y; s0.z += v.z; s0.w += v.w;
        v = p[1]; s1.x += v.x; s1.y += v.y; s1.z += v.z; s1.w += v.w;
        p = base + (size_t)id.y * 2;
        v = p[0]; s0.x += v.x; s0.y += v.y; s0.z += v.z; s0.w += v.w;
        v = p[1]; s1.x += v.x; s1.y += v.y; s1.z += v.z; s1.w += v.w;
        p = base + (size_t)id.z * 2;
        v = p[0]; s0.x += v.x; s0.y += v.y; s0.z += v.z; s0.w += v.w;
        v = p[1]; s1.x += v.x; s1.y += v.y; s1.z += v.z; s1.w += v.w;
        p = base + (size_t)id.w * 2;
        v = p[0]; s0.x += v.x; s0.y += v.y; s0.z += v.z; s0.w += v.w;
        v = p[1]; s1.x += v.x; s1.y += v.y; s1.z += v.z; s1.w += v.w;
    }
}

__device__ __forceinline__ void spmm_body(const float* __restrict__ in,
                                          float* __restrict__ out,
                                          const int* __restrict__ neighbors) {
    int node = blockIdx.x * blockDim.x + threadIdx.x;
    int b = node >> 13;
    const int4* nb = (const int4*)(neighbors + (size_t)node * DEG_);
    const float4* base = (const float4*)(in + (size_t)b * N_ * K_);
    float4 s0, s1;
    gather16(base, nb, s0, s1);
    const float4* am = (const float4*)(g_amps + (size_t)node * K_);
    float4 a0 = am[0], a1 = am[1];
    float4* o = (float4*)(out + (size_t)node * K_);
    o[0] = make_float4(s0.x * a0.x, s0.y * a0.y, s0.z * a0.z, s0.w * a0.w);
    o[1] = make_float4(s1.x * a1.x, s1.y * a1.y, s1.z * a1.z, s1.w * a1.w);
}

__global__ void spmm_step1(const int* __restrict__ neighbors) { spmm_body(g_amps, g_bufA, neighbors); }
__global__ void spmm_step2(const int* __restrict__ neighbors) { spmm_body(g_bufA, g_bufB, neighbors); }

__global__ void spmm_final(const int* __restrict__ neighbors) {
    int node = blockIdx.x * blockDim.x + threadIdx.x;
    int b = node >> 13;
    const int4* nb = (const int4*)(neighbors + (size_t)node * DEG_);
    const float4* base = (const float4*)(g_bufB + (size_t)b * N_ * K_);
    float4 s0, s1;
    gather16(base, nb, s0, s1);
    float absum = fabsf(s0.x) + fabsf(s0.y) + fabsf(s0.z) + fabsf(s0.w)
                + fabsf(s1.x) + fabsf(s1.y) + fabsf(s1.z) + fabsf(s1.w);
    float ss = s0.x * s0.x + s0.y * s0.y + s0.z * s0.z + s0.w * s0.w
             + s1.x * s1.x + s1.y * s1.y + s1.z * s1.z + s1.w * s1.w;
    g_absum[node] = absum;

    __shared__ float red[256];
    int t = threadIdx.x;
    red[t] = ss;
    __syncthreads();
#pragma unroll
    for (int s = 128; s > 0; s >>= 1) {
        if (t < s) red[t] += red[t + s];
        __syncthreads();
    }
    if (t == 0) g_part[blockIdx.x] = red[0];
}

__global__ void reduce_sumsq() {
    int b = threadIdx.x;
    if (b < B_) {
        float s = 0.f;
        for (int i = 0; i < 32; i++) s += g_part[b * 32 + i];
        g_sumsq[b] = s;
    }
}

__global__ void finalize(float* __restrict__ out) {
    int node = blockIdx.x * blockDim.x + threadIdx.x;
    int b = node >> 13;
    float ss = g_sumsq[b];
    float scale = (ss > 0.f) ? rsqrtf(ss) : 1.f;
    out[node] = g_absum[node] * scale;
}

// ---------------- launch ----------------
extern "C" void kernel_launch(void* const* d_in, const int* in_sizes, int n_in,
                              void* d_out, int out_size) {
    const float* q_embs    = (const float*)d_in[0];
    const float* emb       = (const float*)d_in[1];
    const int*   neighbors = (const int*)d_in[2];
    const int*   labels    = (const int*)d_in[3];
    const float* W1        = (const float*)d_in[4];
    const float* b1        = (const float*)d_in[5];
    const float* W2        = (const float*)d_in[6];
    const float* b2        = (const float*)d_in[7];
    const float* P1        = (const float*)d_in[8];
    const float* pb1       = (const float*)d_in[9];
    const float* P2        = (const float*)d_in[10];
    const float* pb2       = (const float*)d_in[11];
    float* out = (float*)d_out;

    cudaFuncSetAttribute(gemm_tc, cudaFuncAttributeMaxDynamicSharedMemorySize, SM_TOTAL);

    prep_wt<<<(WCOLS * D_) / 256, 256>>>(W1, P1);
    prep_qc<<<B_, 256>>>(q_embs, W1, b1, P1, pb1);
    prep_small<<<1, 1024>>>(W2, b2, P2, pb2);
    gemm_tc<<<NODES / MTILE, 512, SM_TOTAL>>>(emb, labels);
    spmm_step1<<<NODES / 256, 256>>>(neighbors);
    spmm_step2<<<NODES / 256, 256>>>(neighbors);
    spmm_final<<<NODES / 256, 256>>>(neighbors);
    reduce_sumsq<<<1, 32>>>();
    finalize<<<NODES / 256, 256>>>(out);
}

// round 8
// speedup vs baseline: 2.0323x; 1.0671x over previous
#include <cuda_runtime.h>
#include <cuda_bf16.h>
#include <math.h>
#include <stdint.h>

#define B_    16
#define N_    8192
#define D_    384
#define DEG_  16
#define K_    8
#define H_    128
#define NODES (B_ * N_)
#define WCOLS 256
#define MTILE 64          // rows per CTA
#define NTILE 128         // cols per CTA (one half)
#define KCH   32
#define NCH   (D_ / KCH)  // 12

// ---- smem layout (bytes) ----
#define SM_QC     0          // 128 f32 (this CTA's col-half)
#define SM_W2     512        // 128x8 f32 (hidden half only)
#define SM_P2     4608       // 128 f32
#define SM_B2     5120       // 8 f32
#define SM_PB2    5152       // 1 f32
#define SM_A      5632       // 2 bufs x (hi 4KB + lo 4KB) = 16KB
#define SM_B      22016      // 2 bufs x (hi 8KB + lo 8KB) = 32KB
#define SM_TOTAL  54784
#define SM_EPART  5632       // reuse A/B region post-loop (hidden: 4x64x8 f32 = 8KB)

__device__ float g_qc[B_ * WCOLS];
__device__ __nv_bfloat16 g_WhiT[WCOLS * D_];   // BT[n][k], k contiguous
__device__ __nv_bfloat16 g_WloT[WCOLS * D_];
__device__ float g_W2[H_ * K_];
__device__ float g_P2[H_];
__device__ float g_b2[K_];
__device__ float g_pb2[1];
__device__ float g_s[NODES * K_];       // layer-2 hidden sums (+b2)
__device__ float g_factor[NODES];       // 1 + sigmoid + label
__device__ float g_amps[NODES * K_];
__device__ float g_bufA[NODES * K_];
__device__ float g_bufB[NODES * K_];
__device__ float g_absum[NODES];
__device__ float g_part[512];
__device__ float g_sumsq[B_];

// ---------------- helpers ----------------
__device__ __forceinline__ uint32_t smem_u32(const void* p) {
    uint32_t a;
    asm("{ .reg .u64 t; cvta.to.shared.u64 t, %1; cvt.u32.u64 %0, t; }" : "=r"(a) : "l"(p));
    return a;
}
__device__ __forceinline__ uint32_t pk2(__nv_bfloat16 a, __nv_bfloat16 b) {
    __nv_bfloat162 t(a, b);
    return *reinterpret_cast<uint32_t*>(&t);
}
// paired-row swizzle: two 64B rows per 128B line, granule-XOR by line.
// r = logical row (64B of k data), g = 16B granule index within row (0..3)
__device__ __forceinline__ uint32_t off64(int r, int g) {
    uint32_t line = (uint32_t)(r >> 1);
    uint32_t col = (uint32_t)(((r & 1) << 6) | (g << 4));
    return line * 128 + (col ^ ((line & 7) << 4));
}
__device__ __forceinline__ void cp16(uint32_t dst, const void* src) {
    asm volatile("cp.async.cg.shared.global [%0], [%1], 16;" :: "r"(dst), "l"(src) : "memory");
}
__device__ __forceinline__ void cp_commit() {
    asm volatile("cp.async.commit_group;" ::: "memory");
}
__device__ __forceinline__ void mma_bf16(float* d, const uint32_t* a, const uint32_t* b) {
    asm volatile(
        "mma.sync.aligned.m16n8k16.row.col.f32.bf16.bf16.f32 "
        "{%0,%1,%2,%3}, {%4,%5,%6,%7}, {%8,%9}, {%0,%1,%2,%3};"
        : "+f"(d[0]), "+f"(d[1]), "+f"(d[2]), "+f"(d[3])
        : "r"(a[0]), "r"(a[1]), "r"(a[2]), "r"(a[3]), "r"(b[0]), "r"(b[1]));
}
__device__ __forceinline__ void ldm_x4(uint32_t& r0, uint32_t& r1, uint32_t& r2, uint32_t& r3,
                                       uint32_t addr) {
    asm volatile("ldmatrix.sync.aligned.m8n8.x4.shared.b16 {%0,%1,%2,%3}, [%4];"
                 : "=r"(r0), "=r"(r1), "=r"(r2), "=r"(r3) : "r"(addr));
}

// ---------------- prep kernels ----------------
__global__ void prep_wt(const float* __restrict__ W1, const float* __restrict__ P1) {
    int i = blockIdx.x * blockDim.x + threadIdx.x;   // 256*384
    int n = i / D_;
    int kd = i - n * D_;
    float v = (n < H_) ? W1[kd * H_ + n] : P1[kd * H_ + (n - H_)];
    __nv_bfloat16 hi = __float2bfloat16(v);
    __nv_bfloat16 lo = __float2bfloat16(v - __bfloat162float(hi));
    g_WhiT[i] = hi;
    g_WloT[i] = lo;
}

__global__ void prep_qc(const float* __restrict__ q,
                        const float* __restrict__ W1, const float* __restrict__ b1,
                        const float* __restrict__ P1, const float* __restrict__ pb1) {
    __shared__ float qs[D_];
    int b = blockIdx.x;
    int j = threadIdx.x;
    for (int d = j; d < D_; d += 256) qs[d] = q[b * D_ + d];
    __syncthreads();
    float s;
    const float* w;
    if (j < H_) { s = b1[j];       w = W1 + (size_t)D_ * H_ + j; }
    else        { s = pb1[j - H_]; w = P1 + (size_t)D_ * H_ + (j - H_); }
#pragma unroll 4
    for (int d = 0; d < D_; d++) s = fmaf(qs[d], w[(size_t)d * H_], s);
    g_qc[b * WCOLS + j] = s;
}

__global__ void prep_small(const float* __restrict__ W2, const float* __restrict__ b2,
                           const float* __restrict__ P2, const float* __restrict__ pb2) {
    int i = threadIdx.x;
    if (i < H_ * K_) g_W2[i] = W2[i];
    if (i < H_) g_P2[i] = P2[i];
    if (i < K_) g_b2[i] = b2[i];
    if (i == 0) g_pb2[0] = pb2[0];
}

// ---------------- GEMM: 64x128 tile / CTA, 256 threads, 8 warps, 3 CTAs/SM ----
// blockIdx.x = rowTile*2 + half.  half 0: hidden cols 0-127, half 1: path cols 128-255.
__global__ __launch_bounds__(256, 3)
void gemm_tc(const float* __restrict__ emb, const int* __restrict__ labels) {
    extern __shared__ char smem[];
    const uint32_t sb = smem_u32(smem);
    const int tid = threadIdx.x;
    const int wid = tid >> 5;
    const int lane = tid & 31;
    const int half = blockIdx.x & 1;
    const int row0 = (blockIdx.x >> 1) * MTILE;
    const int b = row0 >> 13;
    const int nbase = half * NTILE;

    // tables
    if (tid < NTILE) ((float*)(smem + SM_QC))[tid] = g_qc[b * WCOLS + nbase + tid];
#pragma unroll
    for (int j = 0; j < 4; j++)
        ((float*)(smem + SM_W2))[tid * 4 + j] = g_W2[tid * 4 + j];
    if (tid < H_) ((float*)(smem + SM_P2))[tid] = g_P2[tid];
    if (tid < K_) ((float*)(smem + SM_B2))[tid] = g_b2[tid];
    if (tid == 0) *((float*)(smem + SM_PB2)) = g_pb2[0];

    // ---- B chunk prefetch (this CTA's 128-col half) ----
    const __nv_bfloat16* WhiBase = g_WhiT + (size_t)nbase * D_;
    const __nv_bfloat16* WloBase = g_WloT + (size_t)nbase * D_;
    auto issueB = [&](int c, int buf) {
        uint32_t bhi = sb + SM_B + buf * 16384;
        uint32_t blo = bhi + 8192;
#pragma unroll
        for (int i = 0; i < 2; i++) {
            int idx = tid * 2 + i;          // 0..511 granules
            int n = idx >> 2, g = idx & 3;
            uint32_t off = off64(n, g);
            const char* sh = (const char*)(WhiBase + (size_t)n * D_ + c * KCH) + g * 16;
            const char* sl = (const char*)(WloBase + (size_t)n * D_ + c * KCH) + g * 16;
            cp16(bhi + off, sh);
            cp16(blo + off, sl);
        }
        cp_commit();
    };

    issueB(0, 0);
    issueB(1, 1);

    // A staging: thread -> row ar = tid>>2 (0..63), quarter aq = tid&3 (8 floats)
    const int ar = tid >> 2;
    const int aq = tid & 3;
    const float* abase = emb + (size_t)(row0 + ar) * D_ + aq * 8;

    auto stsA = [&](const float4& v0, const float4& v1, int buf) {
        uint32_t ahi = sb + SM_A + buf * 8192;
        uint32_t alo = ahi + 4096;
        float vv[8] = {v0.x, v0.y, v0.z, v0.w, v1.x, v1.y, v1.z, v1.w};
        __nv_bfloat16 h[8], l[8];
#pragma unroll
        for (int i = 0; i < 8; i++) {
            h[i] = __float2bfloat16(vv[i]);
            l[i] = __float2bfloat16(vv[i] - __bfloat162float(h[i]));
        }
        uint32_t o = off64(ar, aq);
        asm volatile("st.shared.v4.b32 [%0], {%1,%2,%3,%4};" :: "r"(ahi + o),
                     "r"(pk2(h[0], h[1])), "r"(pk2(h[2], h[3])),
                     "r"(pk2(h[4], h[5])), "r"(pk2(h[6], h[7])) : "memory");
        asm volatile("st.shared.v4.b32 [%0], {%1,%2,%3,%4};" :: "r"(alo + o),
                     "r"(pk2(l[0], l[1])), "r"(pk2(l[2], l[3])),
                     "r"(pk2(l[4], l[5])), "r"(pk2(l[6], l[7])) : "memory");
    };

    // prologue: A(0) -> buf0; A(1) in regs
    float4 pv0 = *(const float4*)(abase + 0);
    float4 pv1 = *(const float4*)(abase + 4);
    stsA(pv0, pv1, 0);
    pv0 = *(const float4*)(abase + KCH + 0);
    pv1 = *(const float4*)(abase + KCH + 4);

    // accumulators: per-warp 32x32 -> acc[2 mf][4 nf][4]
    float acc[2][4][4];
#pragma unroll
    for (int i = 0; i < 2; i++)
#pragma unroll
        for (int j = 0; j < 4; j++)
#pragma unroll
            for (int k = 0; k < 4; k++) acc[i][j][k] = 0.f;

    const int wm = wid >> 2;        // 0..1 (32-row band)
    const int wn = wid & 3;         // 0..3 (32-col slice)
    const int m0 = wm * 32;
    const int n0w = wn * 32;
    const int g4 = lane >> 2;
    const int t4 = lane & 3;

    // ---- per-lane ldmatrix offsets (precomputed; nonlinear swizzle) ----
    const int lr = lane & 7;
    const int sel = lane >> 3;
    uint32_t aOff[2][2], bOff[2][2];
#pragma unroll
    for (int mf = 0; mf < 2; mf++) {
        int rA = m0 + mf * 16 + lr + ((sel & 1) ? 8 : 0);
#pragma unroll
        for (int ks = 0; ks < 2; ks++) {
            int gA = ks * 2 + ((sel >> 1) & 1);
            aOff[mf][ks] = off64(rA, gA);
        }
    }
#pragma unroll
    for (int nfp = 0; nfp < 2; nfp++) {
        int rB = n0w + nfp * 16 + ((sel >> 1) ? 8 : 0) + lr;
#pragma unroll
        for (int ks = 0; ks < 2; ks++) {
            int gB = ks * 2 + (sel & 1);
            bOff[nfp][ks] = off64(rB, gB);
        }
    }

    for (int c = 0; c < NCH; c++) {
        const int buf = c & 1;
        if (c == NCH - 1) asm volatile("cp.async.wait_group 0;" ::: "memory");
        else              asm volatile("cp.async.wait_group 1;" ::: "memory");

        if (c + 1 < NCH) stsA(pv0, pv1, (c + 1) & 1);
        __syncthreads();

        const uint32_t AhiB = sb + SM_A + buf * 8192;
        const uint32_t AloB = AhiB + 4096;
        const uint32_t BhiB = sb + SM_B + buf * 16384;
        const uint32_t BloB = BhiB + 8192;

#pragma unroll
        for (int ks = 0; ks < 2; ks++) {
            uint32_t ah[2][4], bh[4][2], bl[4][2];
#pragma unroll
            for (int nfp = 0; nfp < 2; nfp++)
                ldm_x4(bh[nfp * 2][0], bh[nfp * 2][1], bh[nfp * 2 + 1][0], bh[nfp * 2 + 1][1],
                       BhiB + bOff[nfp][ks]);
#pragma unroll
            for (int mf = 0; mf < 2; mf++)
                ldm_x4(ah[mf][0], ah[mf][1], ah[mf][2], ah[mf][3], AhiB + aOff[mf][ks]);
#pragma unroll
            for (int mf = 0; mf < 2; mf++)
#pragma unroll
                for (int nf = 0; nf < 4; nf++)
                    mma_bf16(acc[mf][nf], ah[mf], bh[nf]);
#pragma unroll
            for (int nfp = 0; nfp < 2; nfp++)
                ldm_x4(bl[nfp * 2][0], bl[nfp * 2][1], bl[nfp * 2 + 1][0], bl[nfp * 2 + 1][1],
                       BloB + bOff[nfp][ks]);
#pragma unroll
            for (int mf = 0; mf < 2; mf++)
#pragma unroll
                for (int nf = 0; nf < 4; nf++)
                    mma_bf16(acc[mf][nf], ah[mf], bl[nf]);
#pragma unroll
            for (int mf = 0; mf < 2; mf++)
                ldm_x4(ah[mf][0], ah[mf][1], ah[mf][2], ah[mf][3], AloB + aOff[mf][ks]);
#pragma unroll
            for (int mf = 0; mf < 2; mf++)
#pragma unroll
                for (int nf = 0; nf < 4; nf++)
                    mma_bf16(acc[mf][nf], ah[mf], bh[nf]);
        }
        __syncthreads();

        if (c + 2 < NCH) {
            issueB(c + 2, buf);
            const float* nb = abase + (c + 2) * KCH;
            pv0 = *(const float4*)(nb + 0);
            pv1 = *(const float4*)(nb + 4);
        }
    }

    // ---------------- epilogue (per col-half) ----------------
    const float* qcs = (const float*)(smem + SM_QC);
    const float* W2s = (const float*)(smem + SM_W2);
    const float* P2s = (const float*)(smem + SM_P2);
    float* epart = (float*)(smem + SM_EPART);

    if (half == 0) {
        // hidden half: reduce through W2 -> per-row 8 sums
#pragma unroll
        for (int mf = 0; mf < 2; mf++) {
#pragma unroll
            for (int rg = 0; rg < 2; rg++) {
                int rowl = m0 + mf * 16 + g4 + rg * 8;
                float p[8] = {0.f, 0.f, 0.f, 0.f, 0.f, 0.f, 0.f, 0.f};
#pragma unroll
                for (int nf = 0; nf < 4; nf++) {
#pragma unroll
                    for (int cp = 0; cp < 2; cp++) {
                        int lc = n0w + nf * 8 + t4 * 2 + cp;
                        float hv = fmaxf(acc[mf][nf][rg * 2 + cp] + qcs[lc], 0.f);
                        const float* w = W2s + lc * 8;
#pragma unroll
                        for (int k = 0; k < 8; k++) p[k] = fmaf(hv, w[k], p[k]);
                    }
                }
#pragma unroll
                for (int k = 0; k < 8; k++) {
                    p[k] += __shfl_xor_sync(0xffffffffu, p[k], 1);
                    p[k] += __shfl_xor_sync(0xffffffffu, p[k], 2);
                }
                if (t4 == 0) {
#pragma unroll
                    for (int k = 0; k < 8; k++)
                        epart[((size_t)wn * 64 + rowl) * 8 + k] = p[k];
                }
            }
        }
        __syncthreads();
        const float* b2s = (const float*)(smem + SM_B2);
        for (int t = tid; t < 64 * 8; t += 256) {
            int r = t >> 3, k = t & 7;
            float s = epart[(0 * 64 + r) * 8 + k] + epart[(1 * 64 + r) * 8 + k]
                    + epart[(2 * 64 + r) * 8 + k] + epart[(3 * 64 + r) * 8 + k];
            g_s[(size_t)(row0 + r) * K_ + k] = s + b2s[k];
        }
    } else {
        // path half: reduce through P2 -> factor per row
#pragma unroll
        for (int mf = 0; mf < 2; mf++) {
#pragma unroll
            for (int rg = 0; rg < 2; rg++) {
                int rowl = m0 + mf * 16 + g4 + rg * 8;
                float p8 = 0.f;
#pragma unroll
                for (int nf = 0; nf < 4; nf++) {
#pragma unroll
                    for (int cp = 0; cp < 2; cp++) {
                        int lc = n0w + nf * 8 + t4 * 2 + cp;
                        float hv = fmaxf(acc[mf][nf][rg * 2 + cp] + qcs[lc], 0.f);
                        p8 = fmaf(hv, P2s[lc], p8);
                    }
                }
                p8 += __shfl_xor_sync(0xffffffffu, p8, 1);
                p8 += __shfl_xor_sync(0xffffffffu, p8, 2);
                if (t4 == 0) epart[(size_t)wn * 64 + rowl] = p8;
            }
        }
        __syncthreads();
        if (tid < 64) {
            float logit = epart[0 * 64 + tid] + epart[1 * 64 + tid]
                        + epart[2 * 64 + tid] + epart[3 * 64 + tid]
                        + *((const float*)(smem + SM_PB2));
            int row = row0 + tid;
            float factor = 2.f / (1.f + expf(-logit)) - 0.f;   // placeholder? no:
            factor = 1.f + 1.f / (1.f + expf(-logit)) + (float)labels[row];
            g_factor[row] = factor;
        }
    }
}

// ---------------- amps = (s) * factor ----------------
__global__ void finalize_amps() {
    int node = blockIdx.x * blockDim.x + threadIdx.x;
    float f = g_factor[node];
    const float4* s = (const float4*)(g_s + (size_t)node * K_);
    float4 s0 = s[0], s1 = s[1];
    float4* o = (float4*)(g_amps + (size_t)node * K_);
    o[0] = make_float4(s0.x * f, s0.y * f, s0.z * f, s0.w * f);
    o[1] = make_float4(s1.x * f, s1.y * f, s1.z * f, s1.w * f);
}

// ---------------- diffusion (unchanged, L2-resident) ----------------
__device__ __forceinline__ void gather16(const float4* __restrict__ base,
                                         const int4* __restrict__ nb,
                                         float4& s0, float4& s1) {
    s0 = make_float4(0.f, 0.f, 0.f, 0.f);
    s1 = make_float4(0.f, 0.f, 0.f, 0.f);
#pragma unroll
    for (int j = 0; j < 4; j++) {
        int4 id = nb[j];
        const float4* p;
        float4 v;
        p = base + (size_t)id.x * 2;
        v = p[0]; s0.x += v.x; s0.y += v.y; s0.z += v.z; s0.w += v.w;
        v = p[1]; s1.x += v.x; s1.y += v.y; s1.z += v.z; s1.w += v.w;
        p = base + (size_t)id.y * 2;
        v = p[0]; s0.x += v.x; s0.y += v.y; s0.z += v.z; s0.w += v.w;
        v = p[1]; s1.x += v.x; s1.y += v.y; s1.z += v.z; s1.w += v.w;
        p = base + (size_t)id.z * 2;
        v = p[0]; s0.x += v.x; s0.y += v.y; s0.z += v.z; s0.w += v.w;
        v = p[1]; s1.x += v.x; s1.y += v.y; s1.z += v.z; s1.w += v.w;
        p = base + (size_t)id.w * 2;
        v = p[0]; s0.x += v.x; s0.y += v.y; s0.z += v.z; s0.w += v.w;
        v = p[1]; s1.x += v.x; s1.y += v.y; s1.z += v.z; s1.w += v.w;
    }
}

__device__ __forceinline__ void spmm_body(const float* __restrict__ in,
                                          float* __restrict__ out,
                                          const int* __restrict__ neighbors) {
    int node = blockIdx.x * blockDim.x + threadIdx.x;
    int b = node >> 13;
    const int4* nb = (const int4*)(neighbors + (size_t)node * DEG_);
    const float4* base = (const float4*)(in + (size_t)b * N_ * K_);
    float4 s0, s1;
    gather16(base, nb, s0, s1);
    const float4* am = (const float4*)(g_amps + (size_t)node * K_);
    float4 a0 = am[0], a1 = am[1];
    float4* o = (float4*)(out + (size_t)node * K_);
    o[0] = make_float4(s0.x * a0.x, s0.y * a0.y, s0.z * a0.z, s0.w * a0.w);
    o[1] = make_float4(s1.x * a1.x, s1.y * a1.y, s1.z * a1.z, s1.w * a1.w);
}

__global__ void spmm_step1(const int* __restrict__ neighbors) { spmm_body(g_amps, g_bufA, neighbors); }
__global__ void spmm_step2(const int* __restrict__ neighbors) { spmm_body(g_bufA, g_bufB, neighbors); }

__global__ void spmm_final(const int* __restrict__ neighbors) {
    int node = blockIdx.x * blockDim.x + threadIdx.x;
    int b = node >> 13;
    const int4* nb = (const int4*)(neighbors + (size_t)node * DEG_);
    const float4* base = (const float4*)(g_bufB + (size_t)b * N_ * K_);
    float4 s0, s1;
    gather16(base, nb, s0, s1);
    float absum = fabsf(s0.x) + fabsf(s0.y) + fabsf(s0.z) + fabsf(s0.w)
                + fabsf(s1.x) + fabsf(s1.y) + fabsf(s1.z) + fabsf(s1.w);
    float ss = s0.x * s0.x + s0.y * s0.y + s0.z * s0.z + s0.w * s0.w
             + s1.x * s1.x + s1.y * s1.y + s1.z * s1.z + s1.w * s1.w;
    g_absum[node] = absum;

    __shared__ float red[256];
    int t = threadIdx.x;
    red[t] = ss;
    __syncthreads();
#pragma unroll
    for (int s = 128; s > 0; s >>= 1) {
        if (t < s) red[t] += red[t + s];
        __syncthreads();
    }
    if (t == 0) g_part[blockIdx.x] = red[0];
}

__global__ void reduce_sumsq() {
    int b = threadIdx.x;
    if (b < B_) {
        float s = 0.f;
        for (int i = 0; i < 32; i++) s += g_part[b * 32 + i];
        g_sumsq[b] = s;
    }
}

__global__ void finalize(float* __restrict__ out) {
    int node = blockIdx.x * blockDim.x + threadIdx.x;
    int b = node >> 13;
    float ss = g_sumsq[b];
    float scale = (ss > 0.f) ? rsqrtf(ss) : 1.f;
    out[node] = g_absum[node] * scale;
}

// ---------------- launch ----------------
extern "C" void kernel_launch(void* const* d_in, const int* in_sizes, int n_in,
                              void* d_out, int out_size) {
    const float* q_embs    = (const float*)d_in[0];
    const float* emb       = (const float*)d_in[1];
    const int*   neighbors = (const int*)d_in[2];
    const int*   labels    = (const int*)d_in[3];
    const float* W1        = (const float*)d_in[4];
    const float* b1        = (const float*)d_in[5];
    const float* W2        = (const float*)d_in[6];
    const float* b2        = (const float*)d_in[7];
    const float* P1        = (const float*)d_in[8];
    const float* pb1       = (const float*)d_in[9];
    const float* P2        = (const float*)d_in[10];
    const float* pb2       = (const float*)d_in[11];
    float* out = (float*)d_out;

    cudaFuncSetAttribute(gemm_tc, cudaFuncAttributeMaxDynamicSharedMemorySize, SM_TOTAL);

    prep_wt<<<(WCOLS * D_) / 256, 256>>>(W1, P1);
    prep_qc<<<B_, 256>>>(q_embs, W1, b1, P1, pb1);
    prep_small<<<1, 1024>>>(W2, b2, P2, pb2);
    gemm_tc<<<(NODES / MTILE) * 2, 256, SM_TOTAL>>>(emb, labels);
    finalize_amps<<<NODES / 256, 256>>>();
    spmm_step1<<<NODES / 256, 256>>>(neighbors);
    spmm_step2<<<NODES / 256, 256>>>(neighbors);
    spmm_final<<<NODES / 256, 256>>>(neighbors);
    reduce_sumsq<<<1, 32>>>();
    finalize<<<NODES / 256, 256>>>(out);
}

// round 9
// speedup vs baseline: 2.1930x; 1.0791x over previous
#include <cuda_runtime.h>
#include <cuda_fp16.h>
#include <math.h>
#include <stdint.h>

#define B_    16
#define N_    8192
#define D_    384
#define DEG_  16
#define K_    8
#define H_    128
#define NODES (B_ * N_)
#define WCOLS 256
#define MTILE 64          // rows per CTA
#define NTILE 128         // cols per CTA (one half)
#define KCH   32
#define NCH   (D_ / KCH)  // 12
#define WSCALE 1024.0f    // weights pre-scaled by 2^10 (keeps Bl normal in fp16)
#define WINV  (1.0f / 1024.0f)

// ---- smem layout (bytes) ----
#define SM_QC     0          // 128 f32 (this CTA's col-half)
#define SM_W2     512        // 128x8 f32
#define SM_P2     4608       // 128 f32
#define SM_B2     5120       // 8 f32
#define SM_PB2    5152       // 1 f32
#define SM_A      5632       // 2 bufs x 4KB (single fp16) = 8KB
#define SM_B      13824      // 2 bufs x (hi 8KB + lo 8KB) = 32KB
#define SM_TOTAL  46592
#define SM_EPART  5632       // reuse A/B region post-loop

__device__ float g_qc[B_ * WCOLS];
__device__ __half g_WhiT[WCOLS * D_];   // fp16(B*1024) hi, BT[n][k]
__device__ __half g_WloT[WCOLS * D_];   // fp16 residual
__device__ float g_W2[H_ * K_];
__device__ float g_P2[H_];
__device__ float g_b2[K_];
__device__ float g_pb2[1];
__device__ float g_s[NODES * K_];       // layer-2 hidden sums (+b2)
__device__ float g_factor[NODES];       // 1 + sigmoid + label
__device__ float g_amps[NODES * K_];
__device__ float g_bufA[NODES * K_];
__device__ float g_bufB[NODES * K_];
__device__ float g_absum[NODES];
__device__ float g_part[512];

// ---------------- helpers ----------------
__device__ __forceinline__ uint32_t smem_u32(const void* p) {
    uint32_t a;
    asm("{ .reg .u64 t; cvta.to.shared.u64 t, %1; cvt.u32.u64 %0, t; }" : "=r"(a) : "l"(p));
    return a;
}
__device__ __forceinline__ uint32_t pk2h(__half a, __half b) {
    __half2 t(a, b);
    return *reinterpret_cast<uint32_t*>(&t);
}
// paired-row swizzle: two 64B rows per 128B line, granule-XOR by line
__device__ __forceinline__ uint32_t off64(int r, int g) {
    uint32_t line = (uint32_t)(r >> 1);
    uint32_t col = (uint32_t)(((r & 1) << 6) | (g << 4));
    return line * 128 + (col ^ ((line & 7) << 4));
}
__device__ __forceinline__ void cp16(uint32_t dst, const void* src) {
    asm volatile("cp.async.cg.shared.global [%0], [%1], 16;" :: "r"(dst), "l"(src) : "memory");
}
__device__ __forceinline__ void cp_commit() {
    asm volatile("cp.async.commit_group;" ::: "memory");
}
__device__ __forceinline__ void mma_f16(float* d, const uint32_t* a, const uint32_t* b) {
    asm volatile(
        "mma.sync.aligned.m16n8k16.row.col.f32.f16.f16.f32 "
        "{%0,%1,%2,%3}, {%4,%5,%6,%7}, {%8,%9}, {%0,%1,%2,%3};"
        : "+f"(d[0]), "+f"(d[1]), "+f"(d[2]), "+f"(d[3])
        : "r"(a[0]), "r"(a[1]), "r"(a[2]), "r"(a[3]), "r"(b[0]), "r"(b[1]));
}
__device__ __forceinline__ void ldm_x4(uint32_t& r0, uint32_t& r1, uint32_t& r2, uint32_t& r3,
                                       uint32_t addr) {
    asm volatile("ldmatrix.sync.aligned.m8n8.x4.shared.b16 {%0,%1,%2,%3}, [%4];"
                 : "=r"(r0), "=r"(r1), "=r"(r2), "=r"(r3) : "r"(addr));
}

// ---------------- prep kernels ----------------
__global__ void prep_wt(const float* __restrict__ W1, const float* __restrict__ P1) {
    int i = blockIdx.x * blockDim.x + threadIdx.x;   // 256*384
    int n = i / D_;
    int kd = i - n * D_;
    float v = ((n < H_) ? W1[kd * H_ + n] : P1[kd * H_ + (n - H_)]) * WSCALE;
    __half hi = __float2half_rn(v);
    __half lo = __float2half_rn(v - __half2float(hi));
    g_WhiT[i] = hi;
    g_WloT[i] = lo;
}

__global__ void prep_qc(const float* __restrict__ q,
                        const float* __restrict__ W1, const float* __restrict__ b1,
                        const float* __restrict__ P1, const float* __restrict__ pb1) {
    __shared__ float qs[D_];
    int b = blockIdx.x;
    int j = threadIdx.x;
    for (int d = j; d < D_; d += 256) qs[d] = q[b * D_ + d];
    __syncthreads();
    float s;
    const float* w;
    if (j < H_) { s = b1[j];       w = W1 + (size_t)D_ * H_ + j; }
    else        { s = pb1[j - H_]; w = P1 + (size_t)D_ * H_ + (j - H_); }
#pragma unroll 4
    for (int d = 0; d < D_; d++) s = fmaf(qs[d], w[(size_t)d * H_], s);
    g_qc[b * WCOLS + j] = s;
}

__global__ void prep_small(const float* __restrict__ W2, const float* __restrict__ b2,
                           const float* __restrict__ P2, const float* __restrict__ pb2) {
    int i = threadIdx.x;
    if (i < H_ * K_) g_W2[i] = W2[i];
    if (i < H_) g_P2[i] = P2[i];
    if (i < K_) g_b2[i] = b2[i];
    if (i == 0) g_pb2[0] = pb2[0];
}

// ---------------- GEMM: 64x128 tile / CTA, 256 threads, 8 warps, 3 CTAs/SM ----
// blockIdx.x = rowTile*2 + half. half 0: hidden cols, half 1: path cols.
// fp16 2-pass: acc = A_f16 x Bh + A_f16 x Bl  (B pre-scaled by 2^10)
__global__ __launch_bounds__(256, 3)
void gemm_tc(const float* __restrict__ emb, const int* __restrict__ labels) {
    extern __shared__ char smem[];
    const uint32_t sb = smem_u32(smem);
    const int tid = threadIdx.x;
    const int wid = tid >> 5;
    const int lane = tid & 31;
    const int half = blockIdx.x & 1;
    const int row0 = (blockIdx.x >> 1) * MTILE;
    const int b = row0 >> 13;
    const int nbase = half * NTILE;

    // tables
    if (tid < NTILE) ((float*)(smem + SM_QC))[tid] = g_qc[b * WCOLS + nbase + tid];
#pragma unroll
    for (int j = 0; j < 4; j++)
        ((float*)(smem + SM_W2))[tid * 4 + j] = g_W2[tid * 4 + j];
    if (tid < H_) ((float*)(smem + SM_P2))[tid] = g_P2[tid];
    if (tid < K_) ((float*)(smem + SM_B2))[tid] = g_b2[tid];
    if (tid == 0) *((float*)(smem + SM_PB2)) = g_pb2[0];

    // ---- hoisted B-prefetch addressing (chunk-independent) ----
    const __half* WhiBase = g_WhiT + (size_t)nbase * D_;
    const __half* WloBase = g_WloT + (size_t)nbase * D_;
    const int bn0 = (tid * 2) >> 2, bg0 = (tid * 2) & 3;
    const int bn1 = (tid * 2 + 1) >> 2, bg1 = (tid * 2 + 1) & 3;
    const uint32_t bo0 = off64(bn0, bg0);
    const uint32_t bo1 = off64(bn1, bg1);
    const char* srcH0 = (const char*)(WhiBase + (size_t)bn0 * D_) + bg0 * 16;
    const char* srcH1 = (const char*)(WhiBase + (size_t)bn1 * D_) + bg1 * 16;
    const char* srcL0 = (const char*)(WloBase + (size_t)bn0 * D_) + bg0 * 16;
    const char* srcL1 = (const char*)(WloBase + (size_t)bn1 * D_) + bg1 * 16;

    auto issueB = [&](int c, int buf) {
        uint32_t bhi = sb + SM_B + buf * 16384;
        uint32_t blo = bhi + 8192;
        size_t koff = (size_t)c * KCH * 2;   // bytes
        cp16(bhi + bo0, srcH0 + koff);
        cp16(bhi + bo1, srcH1 + koff);
        cp16(blo + bo0, srcL0 + koff);
        cp16(blo + bo1, srcL1 + koff);
        cp_commit();
    };

    issueB(0, 0);
    issueB(1, 1);

    // A staging: thread -> row ar = tid>>2, quarter aq = tid&3 (8 floats -> 8 fp16)
    const int ar = tid >> 2;
    const int aq = tid & 3;
    const float* abase = emb + (size_t)(row0 + ar) * D_ + aq * 8;
    const uint32_t aSts = off64(ar, aq);

    auto stsA = [&](const float4& v0, const float4& v1, int buf) {
        uint32_t ab = sb + SM_A + buf * 4096;
        uint32_t p0 = pk2h(__float2half_rn(v0.x), __float2half_rn(v0.y));
        uint32_t p1 = pk2h(__float2half_rn(v0.z), __float2half_rn(v0.w));
        uint32_t p2 = pk2h(__float2half_rn(v1.x), __float2half_rn(v1.y));
        uint32_t p3 = pk2h(__float2half_rn(v1.z), __float2half_rn(v1.w));
        asm volatile("st.shared.v4.b32 [%0], {%1,%2,%3,%4};" :: "r"(ab + aSts),
                     "r"(p0), "r"(p1), "r"(p2), "r"(p3) : "memory");
    };

    // prologue: A(0) -> buf0; A(1) in regs
    float4 pv0 = *(const float4*)(abase + 0);
    float4 pv1 = *(const float4*)(abase + 4);
    stsA(pv0, pv1, 0);
    pv0 = *(const float4*)(abase + KCH + 0);
    pv1 = *(const float4*)(abase + KCH + 4);

    // accumulators: per-warp 32x32 -> acc[2 mf][4 nf][4]
    float acc[2][4][4];
#pragma unroll
    for (int i = 0; i < 2; i++)
#pragma unroll
        for (int j = 0; j < 4; j++)
#pragma unroll
            for (int k = 0; k < 4; k++) acc[i][j][k] = 0.f;

    const int wm = wid >> 2;
    const int wn = wid & 3;
    const int m0 = wm * 32;
    const int n0w = wn * 32;
    const int g4 = lane >> 2;
    const int t4 = lane & 3;

    // ---- per-lane ldmatrix offsets (precomputed) ----
    const int lr = lane & 7;
    const int sel = lane >> 3;
    uint32_t aOff[2][2], bOff[2][2];
#pragma unroll
    for (int mf = 0; mf < 2; mf++) {
        int rA = m0 + mf * 16 + lr + ((sel & 1) ? 8 : 0);
#pragma unroll
        for (int ks = 0; ks < 2; ks++)
            aOff[mf][ks] = off64(rA, ks * 2 + ((sel >> 1) & 1));
    }
#pragma unroll
    for (int nfp = 0; nfp < 2; nfp++) {
        int rB = n0w + nfp * 16 + ((sel >> 1) ? 8 : 0) + lr;
#pragma unroll
        for (int ks = 0; ks < 2; ks++)
            bOff[nfp][ks] = off64(rB, ks * 2 + (sel & 1));
    }

    for (int c = 0; c < NCH; c++) {
        const int buf = c & 1;
        if (c == NCH - 1) asm volatile("cp.async.wait_group 0;" ::: "memory");
        else              asm volatile("cp.async.wait_group 1;" ::: "memory");

        if (c + 1 < NCH) stsA(pv0, pv1, (c + 1) & 1);
        __syncthreads();

        const uint32_t AB   = sb + SM_A + buf * 4096;
        const uint32_t BhiB = sb + SM_B + buf * 16384;
        const uint32_t BloB = BhiB + 8192;

#pragma unroll
        for (int ks = 0; ks < 2; ks++) {
            uint32_t ah[2][4], bh[4][2], bl[4][2];
#pragma unroll
            for (int nfp = 0; nfp < 2; nfp++)
                ldm_x4(bh[nfp * 2][0], bh[nfp * 2][1], bh[nfp * 2 + 1][0], bh[nfp * 2 + 1][1],
                       BhiB + bOff[nfp][ks]);
#pragma unroll
            for (int mf = 0; mf < 2; mf++)
                ldm_x4(ah[mf][0], ah[mf][1], ah[mf][2], ah[mf][3], AB + aOff[mf][ks]);
#pragma unroll
            for (int mf = 0; mf < 2; mf++)
#pragma unroll
                for (int nf = 0; nf < 4; nf++)
                    mma_f16(acc[mf][nf], ah[mf], bh[nf]);
#pragma unroll
            for (int nfp = 0; nfp < 2; nfp++)
                ldm_x4(bl[nfp * 2][0], bl[nfp * 2][1], bl[nfp * 2 + 1][0], bl[nfp * 2 + 1][1],
                       BloB + bOff[nfp][ks]);
#pragma unroll
            for (int mf = 0; mf < 2; mf++)
#pragma unroll
                for (int nf = 0; nf < 4; nf++)
                    mma_f16(acc[mf][nf], ah[mf], bl[nf]);
        }
        __syncthreads();

        if (c + 2 < NCH) {
            issueB(c + 2, buf);
            const float* nb = abase + (c + 2) * KCH;
            pv0 = *(const float4*)(nb + 0);
            pv1 = *(const float4*)(nb + 4);
        }
    }

    // ---------------- epilogue (per col-half); acc scaled by 2^-10 ----------------
    const float* qcs = (const float*)(smem + SM_QC);
    const float* W2s = (const float*)(smem + SM_W2);
    const float* P2s = (const float*)(smem + SM_P2);
    float* epart = (float*)(smem + SM_EPART);

    if (half == 0) {
#pragma unroll
        for (int mf = 0; mf < 2; mf++) {
#pragma unroll
            for (int rg = 0; rg < 2; rg++) {
                int rowl = m0 + mf * 16 + g4 + rg * 8;
                float p[8] = {0.f, 0.f, 0.f, 0.f, 0.f, 0.f, 0.f, 0.f};
#pragma unroll
                for (int nf = 0; nf < 4; nf++) {
#pragma unroll
                    for (int cp = 0; cp < 2; cp++) {
                        int lc = n0w + nf * 8 + t4 * 2 + cp;
                        float hv = fmaxf(fmaf(acc[mf][nf][rg * 2 + cp], WINV, qcs[lc]), 0.f);
                        const float* w = W2s + lc * 8;
#pragma unroll
                        for (int k = 0; k < 8; k++) p[k] = fmaf(hv, w[k], p[k]);
                    }
                }
#pragma unroll
                for (int k = 0; k < 8; k++) {
                    p[k] += __shfl_xor_sync(0xffffffffu, p[k], 1);
                    p[k] += __shfl_xor_sync(0xffffffffu, p[k], 2);
                }
                if (t4 == 0) {
#pragma unroll
                    for (int k = 0; k < 8; k++)
                        epart[((size_t)wn * 64 + rowl) * 8 + k] = p[k];
                }
            }
        }
        __syncthreads();
        const float* b2s = (const float*)(smem + SM_B2);
        for (int t = tid; t < 64 * 8; t += 256) {
            int r = t >> 3, k = t & 7;
            float s = epart[(0 * 64 + r) * 8 + k] + epart[(1 * 64 + r) * 8 + k]
                    + epart[(2 * 64 + r) * 8 + k] + epart[(3 * 64 + r) * 8 + k];
            g_s[(size_t)(row0 + r) * K_ + k] = s + b2s[k];
        }
    } else {
#pragma unroll
        for (int mf = 0; mf < 2; mf++) {
#pragma unroll
            for (int rg = 0; rg < 2; rg++) {
                int rowl = m0 + mf * 16 + g4 + rg * 8;
                float p8 = 0.f;
#pragma unroll
                for (int nf = 0; nf < 4; nf++) {
#pragma unroll
                    for (int cp = 0; cp < 2; cp++) {
                        int lc = n0w + nf * 8 + t4 * 2 + cp;
                        float hv = fmaxf(fmaf(acc[mf][nf][rg * 2 + cp], WINV, qcs[lc]), 0.f);
                        p8 = fmaf(hv, P2s[lc], p8);
                    }
                }
                p8 += __shfl_xor_sync(0xffffffffu, p8, 1);
                p8 += __shfl_xor_sync(0xffffffffu, p8, 2);
                if (t4 == 0) epart[(size_t)wn * 64 + rowl] = p8;
            }
        }
        __syncthreads();
        if (tid < 64) {
            float logit = epart[0 * 64 + tid] + epart[1 * 64 + tid]
                        + epart[2 * 64 + tid] + epart[3 * 64 + tid]
                        + *((const float*)(smem + SM_PB2));
            int row = row0 + tid;
            float factor = 1.f + 1.f / (1.f + expf(-logit)) + (float)labels[row];
            g_factor[row] = factor;
        }
    }
}

// ---------------- amps = s * factor ----------------
__global__ void finalize_amps() {
    int node = blockIdx.x * blockDim.x + threadIdx.x;
    float f = g_factor[node];
    const float4* s = (const float4*)(g_s + (size_t)node * K_);
    float4 s0 = s[0], s1 = s[1];
    float4* o = (float4*)(g_amps + (size_t)node * K_);
    o[0] = make_float4(s0.x * f, s0.y * f, s0.z * f, s0.w * f);
    o[1] = make_float4(s1.x * f, s1.y * f, s1.z * f, s1.w * f);
}

// ---------------- diffusion (L2-resident) ----------------
__device__ __forceinline__ void gather16(const float4* __restrict__ base,
                                         const int4* __restrict__ nb,
                                         float4& s0, float4& s1) {
    s0 = make_float4(0.f, 0.f, 0.f, 0.f);
    s1 = make_float4(0.f, 0.f, 0.f, 0.f);
#pragma unroll
    for (int j = 0; j < 4; j++) {
        int4 id = nb[j];
        const float4* p;
        float4 v;
        p = base + (size_t)id.x * 2;
        v = p[0]; s0.x += v.x; s0.y += v.y; s0.z += v.z; s0.w += v.w;
        v = p[1]; s1.x += v.x; s1.y += v.y; s1.z += v.z; s1.w += v.w;
        p = base + (size_t)id.y * 2;
        v = p[0]; s0.x += v.x; s0.y += v.y; s0.z += v.z; s0.w += v.w;
        v = p[1]; s1.x += v.x; s1.y += v.y; s1.z += v.z; s1.w += v.w;
        p = base + (size_t)id.z * 2;
        v = p[0]; s0.x += v.x; s0.y += v.y; s0.z += v.z; s0.w += v.w;
        v = p[1]; s1.x += v.x; s1.y += v.y; s1.z += v.z; s1.w += v.w;
        p = base + (size_t)id.w * 2;
        v = p[0]; s0.x += v.x; s0.y += v.y; s0.z += v.z; s0.w += v.w;
        v = p[1]; s1.x += v.x; s1.y += v.y; s1.z += v.z; s1.w += v.w;
    }
}

__device__ __forceinline__ void spmm_body(const float* __restrict__ in,
                                          float* __restrict__ out,
                                          const int* __restrict__ neighbors) {
    int node = blockIdx.x * blockDim.x + threadIdx.x;
    int b = node >> 13;
    const int4* nb = (const int4*)(neighbors + (size_t)node * DEG_);
    const float4* base = (const float4*)(in + (size_t)b * N_ * K_);
    float4 s0, s1;
    gather16(base, nb, s0, s1);
    const float4* am = (const float4*)(g_amps + (size_t)node * K_);
    float4 a0 = am[0], a1 = am[1];
    float4* o = (float4*)(out + (size_t)node * K_);
    o[0] = make_float4(s0.x * a0.x, s0.y * a0.y, s0.z * a0.z, s0.w * a0.w);
    o[1] = make_float4(s1.x * a1.x, s1.y * a1.y, s1.z * a1.z, s1.w * a1.w);
}

__global__ void spmm_step1(const int* __restrict__ neighbors) { spmm_body(g_amps, g_bufA, neighbors); }
__global__ void spmm_step2(const int* __restrict__ neighbors) { spmm_body(g_bufA, g_bufB, neighbors); }

__global__ void spmm_final(const int* __restrict__ neighbors) {
    int node = blockIdx.x * blockDim.x + threadIdx.x;
    int b = node >> 13;
    const int4* nb = (const int4*)(neighbors + (size_t)node * DEG_);
    const float4* base = (const float4*)(g_bufB + (size_t)b * N_ * K_);
    float4 s0, s1;
    gather16(base, nb, s0, s1);
    float absum = fabsf(s0.x) + fabsf(s0.y) + fabsf(s0.z) + fabsf(s0.w)
                + fabsf(s1.x) + fabsf(s1.y) + fabsf(s1.z) + fabsf(s1.w);
    float ss = s0.x * s0.x + s0.y * s0.y + s0.z * s0.z + s0.w * s0.w
             + s1.x * s1.x + s1.y * s1.y + s1.z * s1.z + s1.w * s1.w;
    g_absum[node] = absum;

    __shared__ float red[256];
    int t = threadIdx.x;
    red[t] = ss;
    __syncthreads();
#pragma unroll
    for (int s = 128; s > 0; s >>= 1) {
        if (t < s) red[t] += red[t + s];
        __syncthreads();
    }
    if (t == 0) g_part[blockIdx.x] = red[0];
}

__global__ void finalize(float* __restrict__ out) {
    __shared__ float ssum;
    int node = blockIdx.x * blockDim.x + threadIdx.x;
    int b = node >> 13;
    if (threadIdx.x < 32) {
        float s = g_part[b * 32 + threadIdx.x];
#pragma unroll
        for (int off = 16; off > 0; off >>= 1)
            s += __shfl_xor_sync(0xffffffffu, s, off);
        if (threadIdx.x == 0) ssum = s;
    }
    __syncthreads();
    float ss = ssum;
    float scale = (ss > 0.f) ? rsqrtf(ss) : 1.f;
    out[node] = g_absum[node] * scale;
}

// ---------------- launch ----------------
extern "C" void kernel_launch(void* const* d_in, const int* in_sizes, int n_in,
                              void* d_out, int out_size) {
    const float* q_embs    = (const float*)d_in[0];
    const float* emb       = (const float*)d_in[1];
    const int*   neighbors = (const int*)d_in[2];
    const int*   labels    = (const int*)d_in[3];
    const float* W1        = (const float*)d_in[4];
    const float* b1        = (const float*)d_in[5];
    const float* W2        = (const float*)d_in[6];
    const float* b2        = (const float*)d_in[7];
    const float* P1        = (const float*)d_in[8];
    const float* pb1       = (const float*)d_in[9];
    const float* P2        = (const float*)d_in[10];
    const float* pb2       = (const float*)d_in[11];
    float* out = (float*)d_out;

    cudaFuncSetAttribute(gemm_tc, cudaFuncAttributeMaxDynamicSharedMemorySize, SM_TOTAL);

    prep_wt<<<(WCOLS * D_) / 256, 256>>>(W1, P1);
    prep_qc<<<B_, 256>>>(q_embs, W1, b1, P1, pb1);
    prep_small<<<1, 1024>>>(W2, b2, P2, pb2);
    gemm_tc<<<(NODES / MTILE) * 2, 256, SM_TOTAL>>>(emb, labels);
    finalize_amps<<<NODES / 256, 256>>>();
    spmm_step1<<<NODES / 256, 256>>>(neighbors);
    spmm_step2<<<NODES / 256, 256>>>(neighbors);
    spmm_final<<<NODES / 256, 256>>>(neighbors);
    finalize<<<NODES / 256, 256>>>(out);
}

// round 11
// speedup vs baseline: 2.4499x; 1.1172x over previous
#include <cuda_runtime.h>
#include <cuda_fp16.h>
#include <math.h>
#include <stdint.h>

#define B_    16
#define N_    8192
#define D_    384
#define DEG_  16
#define K_    8
#define H_    128
#define NODES (B_ * N_)
#define WCOLS 256
#define MTILE 64          // rows per CTA
#define NTILE 128         // cols per CTA (one half)
#define KCH   32
#define NCH   (D_ / KCH)  // 12
#define WSCALE 1024.0f
#define WINV  (1.0f / 1024.0f)

// ---- smem layout (bytes) ----
#define SM_QC     0          // 128 f32
#define SM_W2     512        // 128x8 f32
#define SM_P2     4608       // 128 f32
#define SM_B2     5120       // 8 f32
#define SM_PB2    5152       // 1 f32
#define SM_A      5632       // 3 bufs x 4KB = 12KB
#define SM_B      17920      // 3 bufs x (hi 8KB + lo 8KB) = 48KB
#define SM_TOTAL  67072
#define SM_EPART  5632       // reuse A region post-loop (8KB needed, 12KB avail)

__device__ float g_qc[B_ * WCOLS];
__device__ __half g_WhiT[WCOLS * D_];   // fp16(B*1024) hi, BT[n][k]
__device__ __half g_WloT[WCOLS * D_];   // fp16 residual
__device__ float g_W2[H_ * K_];
__device__ float g_P2[H_];
__device__ float g_b2[K_];
__device__ float g_pb2[1];
__device__ float g_s[NODES * K_];
__device__ float g_factor[NODES];
__device__ float g_amps[NODES * K_];
__device__ float g_bufA[NODES * K_];
__device__ float g_bufB[NODES * K_];
__device__ float g_absum[NODES];
__device__ float g_part[512];

// ---------------- helpers ----------------
__device__ __forceinline__ uint32_t smem_u32(const void* p) {
    uint32_t a;
    asm("{ .reg .u64 t; cvta.to.shared.u64 t, %1; cvt.u32.u64 %0, t; }" : "=r"(a) : "l"(p));
    return a;
}
__device__ __forceinline__ uint32_t pk2h(__half a, __half b) {
    __half2 t(a, b);
    return *reinterpret_cast<uint32_t*>(&t);
}
// paired-row swizzle: two 64B rows per 128B line, granule-XOR by line
__device__ __forceinline__ uint32_t off64(int r, int g) {
    uint32_t line = (uint32_t)(r >> 1);
    uint32_t col = (uint32_t)(((r & 1) << 6) | (g << 4));
    return line * 128 + (col ^ ((line & 7) << 4));
}
__device__ __forceinline__ void cp16(uint32_t dst, const void* src) {
    asm volatile("cp.async.cg.shared.global [%0], [%1], 16;" :: "r"(dst), "l"(src) : "memory");
}
__device__ __forceinline__ void cp_commit() {
    asm volatile("cp.async.commit_group;" ::: "memory");
}
__device__ __forceinline__ void mma_f16(float* d, const uint32_t* a, const uint32_t* b) {
    asm volatile(
        "mma.sync.aligned.m16n8k16.row.col.f32.f16.f16.f32 "
        "{%0,%1,%2,%3}, {%4,%5,%6,%7}, {%8,%9}, {%0,%1,%2,%3};"
        : "+f"(d[0]), "+f"(d[1]), "+f"(d[2]), "+f"(d[3])
        : "r"(a[0]), "r"(a[1]), "r"(a[2]), "r"(a[3]), "r"(b[0]), "r"(b[1]));
}
__device__ __forceinline__ void ldm_x4(uint32_t& r0, uint32_t& r1, uint32_t& r2, uint32_t& r3,
                                       uint32_t addr) {
    asm volatile("ldmatrix.sync.aligned.m8n8.x4.shared.b16 {%0,%1,%2,%3}, [%4];"
                 : "=r"(r0), "=r"(r1), "=r"(r2), "=r"(r3) : "r"(addr));
}

// ---------------- prep kernels ----------------
__global__ void prep_wt(const float* __restrict__ W1, const float* __restrict__ P1) {
    int i = blockIdx.x * blockDim.x + threadIdx.x;   // 256*384
    int n = i / D_;
    int kd = i - n * D_;
    float v = ((n < H_) ? W1[kd * H_ + n] : P1[kd * H_ + (n - H_)]) * WSCALE;
    __half hi = __float2half_rn(v);
    __half lo = __float2half_rn(v - __half2float(hi));
    g_WhiT[i] = hi;
    g_WloT[i] = lo;
}

__global__ void prep_qc(const float* __restrict__ q,
                        const float* __restrict__ W1, const float* __restrict__ b1,
                        const float* __restrict__ P1, const float* __restrict__ pb1) {
    __shared__ float qs[D_];
    int b = blockIdx.x;
    int j = threadIdx.x;
    for (int d = j; d < D_; d += 256) qs[d] = q[b * D_ + d];
    __syncthreads();
    float s;
    const float* w;
    if (j < H_) { s = b1[j];       w = W1 + (size_t)D_ * H_ + j; }
    else        { s = pb1[j - H_]; w = P1 + (size_t)D_ * H_ + (j - H_); }
#pragma unroll 4
    for (int d = 0; d < D_; d++) s = fmaf(qs[d], w[(size_t)d * H_], s);
    g_qc[b * WCOLS + j] = s;
}

__global__ void prep_small(const float* __restrict__ W2, const float* __restrict__ b2,
                           const float* __restrict__ P2, const float* __restrict__ pb2) {
    int i = threadIdx.x;
    if (i < H_ * K_) g_W2[i] = W2[i];
    if (i < H_) g_P2[i] = P2[i];
    if (i < K_) g_b2[i] = b2[i];
    if (i == 0) g_pb2[0] = pb2[0];
}

// ---------------- GEMM: 64x128 tile / CTA, 256 threads, 8 warps, 3 CTAs/SM ----
// triple-buffered, ONE __syncthreads per chunk, LDG hoisted a full chunk ahead.
__global__ __launch_bounds__(256, 3)
void gemm_tc(const float* __restrict__ emb, const int* __restrict__ labels) {
    extern __shared__ char smem[];
    const uint32_t sb = smem_u32(smem);
    const int tid = threadIdx.x;
    const int wid = tid >> 5;
    const int lane = tid & 31;
    const int half = blockIdx.x & 1;
    const int row0 = (blockIdx.x >> 1) * MTILE;
    const int b = row0 >> 13;
    const int nbase = half * NTILE;

    // tables
    if (tid < NTILE) ((float*)(smem + SM_QC))[tid] = g_qc[b * WCOLS + nbase + tid];
#pragma unroll
    for (int j = 0; j < 4; j++)
        ((float*)(smem + SM_W2))[tid * 4 + j] = g_W2[tid * 4 + j];
    if (tid < H_) ((float*)(smem + SM_P2))[tid] = g_P2[tid];
    if (tid < K_) ((float*)(smem + SM_B2))[tid] = g_b2[tid];
    if (tid == 0) *((float*)(smem + SM_PB2)) = g_pb2[0];

    // ---- hoisted B-prefetch addressing ----
    const __half* WhiBase = g_WhiT + (size_t)nbase * D_;
    const __half* WloBase = g_WloT + (size_t)nbase * D_;
    const int bn0 = (tid * 2) >> 2, bg0 = (tid * 2) & 3;
    const int bn1 = (tid * 2 + 1) >> 2, bg1 = (tid * 2 + 1) & 3;
    const uint32_t bo0 = off64(bn0, bg0);
    const uint32_t bo1 = off64(bn1, bg1);
    const char* srcH0 = (const char*)(WhiBase + (size_t)bn0 * D_) + bg0 * 16;
    const char* srcH1 = (const char*)(WhiBase + (size_t)bn1 * D_) + bg1 * 16;
    const char* srcL0 = (const char*)(WloBase + (size_t)bn0 * D_) + bg0 * 16;
    const char* srcL1 = (const char*)(WloBase + (size_t)bn1 * D_) + bg1 * 16;

    auto issueB = [&](int c, int buf) {
        uint32_t bhi = sb + SM_B + buf * 16384;
        uint32_t blo = bhi + 8192;
        size_t koff = (size_t)c * KCH * 2;
        cp16(bhi + bo0, srcH0 + koff);
        cp16(bhi + bo1, srcH1 + koff);
        cp16(blo + bo0, srcL0 + koff);
        cp16(blo + bo1, srcL1 + koff);
        cp_commit();
    };

    // A staging
    const int ar = tid >> 2;
    const int aq = tid & 3;
    const float* abase = emb + (size_t)(row0 + ar) * D_ + aq * 8;
    const uint32_t aSts = off64(ar, aq);

    auto stsA = [&](const float4& v0, const float4& v1, int buf) {
        uint32_t ab = sb + SM_A + buf * 4096;
        uint32_t p0 = pk2h(__float2half_rn(v0.x), __float2half_rn(v0.y));
        uint32_t p1 = pk2h(__float2half_rn(v0.z), __float2half_rn(v0.w));
        uint32_t p2 = pk2h(__float2half_rn(v1.x), __float2half_rn(v1.y));
        uint32_t p3 = pk2h(__float2half_rn(v1.z), __float2half_rn(v1.w));
        asm volatile("st.shared.v4.b32 [%0], {%1,%2,%3,%4};" :: "r"(ab + aSts),
                     "r"(p0), "r"(p1), "r"(p2), "r"(p3) : "memory");
    };

    // prologue: B0->buf0, B1->buf1; A0->smem buf0; A1 in regs
    issueB(0, 0);
    issueB(1, 1);
    float4 pv0 = *(const float4*)(abase + 0);
    float4 pv1 = *(const float4*)(abase + 4);
    stsA(pv0, pv1, 0);
    pv0 = *(const float4*)(abase + KCH + 0);
    pv1 = *(const float4*)(abase + KCH + 4);

    // accumulators
    float acc[2][4][4];
#pragma unroll
    for (int i = 0; i < 2; i++)
#pragma unroll
        for (int j = 0; j < 4; j++)
#pragma unroll
            for (int k = 0; k < 4; k++) acc[i][j][k] = 0.f;

    const int wm = wid >> 2;
    const int wn = wid & 3;
    const int m0 = wm * 32;
    const int n0w = wn * 32;
    const int g4 = lane >> 2;
    const int t4 = lane & 3;

    // per-lane ldmatrix offsets
    const int lr = lane & 7;
    const int sel = lane >> 3;
    uint32_t aOff[2][2], bOff[2][2];
#pragma unroll
    for (int mf = 0; mf < 2; mf++) {
        int rA = m0 + mf * 16 + lr + ((sel & 1) ? 8 : 0);
#pragma unroll
        for (int ks = 0; ks < 2; ks++)
            aOff[mf][ks] = off64(rA, ks * 2 + ((sel >> 1) & 1));
    }
#pragma unroll
    for (int nfp = 0; nfp < 2; nfp++) {
        int rB = n0w + nfp * 16 + ((sel >> 1) ? 8 : 0) + lr;
#pragma unroll
        for (int ks = 0; ks < 2; ks++)
            bOff[nfp][ks] = off64(rB, ks * 2 + (sel & 1));
    }

    int bufc = 0;   // c % 3
    for (int c = 0; c < NCH; c++) {
        // B(c) resident?  pending groups before issueB(c+2): B(c), B(c+1)
        if (c == NCH - 1) asm volatile("cp.async.wait_group 0;" ::: "memory");
        else              asm volatile("cp.async.wait_group 1;" ::: "memory");
        __syncthreads();    // publish stsA(A(c)) + B(c); all warps done with mma(c-1)

        {
            int buf2 = bufc + 2; if (buf2 >= 3) buf2 -= 3;
            int buf1 = bufc + 1; if (buf1 >= 3) buf1 -= 3;
            if (c + 2 < NCH) issueB(c + 2, buf2);           // safe: mma(c-1) reads done
            if (c + 1 < NCH) stsA(pv0, pv1, buf1);          // safe: mma(c-2) reads done
            if (c + 2 < NCH) {                              // full-chunk LDG slack
                const float* nb = abase + (c + 2) * KCH;
                pv0 = *(const float4*)(nb + 0);
                pv1 = *(const float4*)(nb + 4);
            }
        }

        const uint32_t AB   = sb + SM_A + bufc * 4096;
        const uint32_t BhiB = sb + SM_B + bufc * 16384;
        const uint32_t BloB = BhiB + 8192;

#pragma unroll
        for (int ks = 0; ks < 2; ks++) {
            uint32_t ah[2][4], bh[4][2], bl[4][2];
#pragma unroll
            for (int nfp = 0; nfp < 2; nfp++)
                ldm_x4(bh[nfp * 2][0], bh[nfp * 2][1], bh[nfp * 2 + 1][0], bh[nfp * 2 + 1][1],
                       BhiB + bOff[nfp][ks]);
#pragma unroll
            for (int mf = 0; mf < 2; mf++)
                ldm_x4(ah[mf][0], ah[mf][1], ah[mf][2], ah[mf][3], AB + aOff[mf][ks]);
#pragma unroll
            for (int mf = 0; mf < 2; mf++)
#pragma unroll
                for (int nf = 0; nf < 4; nf++)
                    mma_f16(acc[mf][nf], ah[mf], bh[nf]);
#pragma unroll
            for (int nfp = 0; nfp < 2; nfp++)
                ldm_x4(bl[nfp * 2][0], bl[nfp * 2][1], bl[nfp * 2 + 1][0], bl[nfp * 2 + 1][1],
                       BloB + bOff[nfp][ks]);
#pragma unroll
            for (int mf = 0; mf < 2; mf++)
#pragma unroll
                for (int nf = 0; nf < 4; nf++)
                    mma_f16(acc[mf][nf], ah[mf], bl[nf]);
        }
        if (++bufc == 3) bufc = 0;
    }
    __syncthreads();    // protect EPART reuse of A region

    // ---------------- epilogue ----------------
    const float* qcs = (const float*)(smem + SM_QC);
    const float* W2s = (const float*)(smem + SM_W2);
    const float* P2s = (const float*)(smem + SM_P2);
    float* epart = (float*)(smem + SM_EPART);

    if (half == 0) {
#pragma unroll
        for (int mf = 0; mf < 2; mf++) {
#pragma unroll
            for (int rg = 0; rg < 2; rg++) {
                int rowl = m0 + mf * 16 + g4 + rg * 8;
                float p[8] = {0.f, 0.f, 0.f, 0.f, 0.f, 0.f, 0.f, 0.f};
#pragma unroll
                for (int nf = 0; nf < 4; nf++) {
#pragma unroll
                    for (int cp = 0; cp < 2; cp++) {
                        int lc = n0w + nf * 8 + t4 * 2 + cp;
                        float hv = fmaxf(fmaf(acc[mf][nf][rg * 2 + cp], WINV, qcs[lc]), 0.f);
                        const float* w = W2s + lc * 8;
#pragma unroll
                        for (int k = 0; k < 8; k++) p[k] = fmaf(hv, w[k], p[k]);
                    }
                }
#pragma unroll
                for (int k = 0; k < 8; k++) {
                    p[k] += __shfl_xor_sync(0xffffffffu, p[k], 1);
                    p[k] += __shfl_xor_sync(0xffffffffu, p[k], 2);
                }
                if (t4 == 0) {
#pragma unroll
                    for (int k = 0; k < 8; k++)
                        epart[((size_t)wn * 64 + rowl) * 8 + k] = p[k];
                }
            }
        }
        __syncthreads();
        const float* b2s = (const float*)(smem + SM_B2);
        for (int t = tid; t < 64 * 8; t += 256) {
            int r = t >> 3, k = t & 7;
            float s = epart[(0 * 64 + r) * 8 + k] + epart[(1 * 64 + r) * 8 + k]
                    + epart[(2 * 64 + r) * 8 + k] + epart[(3 * 64 + r) * 8 + k];
            g_s[(size_t)(row0 + r) * K_ + k] = s + b2s[k];
        }
    } else {
#pragma unroll
        for (int mf = 0; mf < 2; mf++) {
#pragma unroll
            for (int rg = 0; rg < 2; rg++) {
                int rowl = m0 + mf * 16 + g4 + rg * 8;
                float p8 = 0.f;
#pragma unroll
                for (int nf = 0; nf < 4; nf++) {
#pragma unroll
                    for (int cp = 0; cp < 2; cp++) {
                        int lc = n0w + nf * 8 + t4 * 2 + cp;
                        float hv = fmaxf(fmaf(acc[mf][nf][rg * 2 + cp], WINV, qcs[lc]), 0.f);
                        p8 = fmaf(hv, P2s[lc], p8);
                    }
                }
                p8 += __shfl_xor_sync(0xffffffffu, p8, 1);
                p8 += __shfl_xor_sync(0xffffffffu, p8, 2);
                if (t4 == 0) epart[(size_t)wn * 64 + rowl] = p8;
            }
        }
        __syncthreads();
        if (tid < 64) {
            float logit = epart[0 * 64 + tid] + epart[1 * 64 + tid]
                        + epart[2 * 64 + tid] + epart[3 * 64 + tid]
                        + *((const float*)(smem + SM_PB2));
            int row = row0 + tid;
            float factor = 1.f + 1.f / (1.f + expf(-logit)) + (float)labels[row];
            g_factor[row] = factor;
        }
    }
}

// ---------------- amps = s * factor ----------------
__global__ void finalize_amps() {
    int node = blockIdx.x * blockDim.x + threadIdx.x;
    float f = g_factor[node];
    const float4* s = (const float4*)(g_s + (size_t)node * K_);
    float4 s0 = s[0], s1 = s[1];
    float4* o = (float4*)(g_amps + (size_t)node * K_);
    o[0] = make_float4(s0.x * f, s0.y * f, s0.z * f, s0.w * f);
    o[1] = make_float4(s1.x * f, s1.y * f, s1.z * f, s1.w * f);
}

// ---------------- diffusion ----------------
__device__ __forceinline__ void gather16(const float4* __restrict__ base,
                                         const int4* __restrict__ nb,
                                         float4& s0, float4& s1) {
    s0 = make_float4(0.f, 0.f, 0.f, 0.f);
    s1 = make_float4(0.f, 0.f, 0.f, 0.f);
#pragma unroll
    for (int j = 0; j < 4; j++) {
        int4 id = nb[j];
        const float4* p;
        float4 v;
        p = base + (size_t)id.x * 2;
        v = p[0]; s0.x += v.x; s0.y += v.y; s0.z += v.z; s0.w += v.w;
        v = p[1]; s1.x += v.x; s1.y += v.y; s1.z += v.z; s1.w += v.w;
        p = base + (size_t)id.y * 2;
        v = p[0]; s0.x += v.x; s0.y += v.y; s0.z += v.z; s0.w += v.w;
        v = p[1]; s1.x += v.x; s1.y += v.y; s1.z += v.z; s1.w += v.w;
        p = base + (size_t)id.z * 2;
        v = p[0]; s0.x += v.x; s0.y += v.y; s0.z += v.z; s0.w += v.w;
        v = p[1]; s1.x += v.x; s1.y += v.y; s1.z += v.z; s1.w += v.w;
        p = base + (size_t)id.w * 2;
        v = p[0]; s0.x += v.x; s0.y += v.y; s0.z += v.z; s0.w += v.w;
        v = p[1]; s1.x += v.x; s1.y += v.y; s1.z += v.z; s1.w += v.w;
    }
}

__device__ __forceinline__ void spmm_body(const float* __restrict__ in,
                                          float* __restrict__ out,
                                          const int* __restrict__ neighbors) {
    int node = blockIdx.x * blockDim.x + threadIdx.x;
    int b = node >> 13;
    const int4* nb = (const int4*)(neighbors + (size_t)node * DEG_);
    const float4* base = (const float4*)(in + (size_t)b * N_ * K_);
    float4 s0, s1;
    gather16(base, nb, s0, s1);
    const float4* am = (const float4*)(g_amps + (size_t)node * K_);
    float4 a0 = am[0], a1 = am[1];
    float4* o = (float4*)(out + (size_t)node * K_);
    o[0] = make_float4(s0.x * a0.x, s0.y * a0.y, s0.z * a0.z, s0.w * a0.w);
    o[1] = make_float4(s1.x * a1.x, s1.y * a1.y, s1.z * a1.z, s1.w * a1.w);
}

__global__ void spmm_step1(const int* __restrict__ neighbors) { spmm_body(g_amps, g_bufA, neighbors); }
__global__ void spmm_step2(const int* __restrict__ neighbors) { spmm_body(g_bufA, g_bufB, neighbors); }

__global__ void spmm_final(const int* __restrict__ neighbors) {
    int node = blockIdx.x * blockDim.x + threadIdx.x;
    int b = node >> 13;
    const int4* nb = (const int4*)(neighbors + (size_t)node * DEG_);
    const float4* base = (const float4*)(g_bufB + (size_t)b * N_ * K_);
    float4 s0, s1;
    gather16(base, nb, s0, s1);
    float absum = fabsf(s0.x) + fabsf(s0.y) + fabsf(s0.z) + fabsf(s0.w)
                + fabsf(s1.x) + fabsf(s1.y) + fabsf(s1.z) + fabsf(s1.w);
    float ss = s0.x * s0.x + s0.y * s0.y + s0.z * s0.z + s0.w * s0.w
             + s1.x * s1.x + s1.y * s1.y + s1.z * s1.z + s1.w * s1.w;
    g_absum[node] = absum;

    __shared__ float red[256];
    int t = threadIdx.x;
    red[t] = ss;
    __syncthreads();
#pragma unroll
    for (int s = 128; s > 0; s >>= 1) {
        if (t < s) red[t] += red[t + s];
        __syncthreads();
    }
    if (t == 0) g_part[blockIdx.x] = red[0];
}

__global__ void finalize(float* __restrict__ out) {
    __shared__ float ssum;
    int node = blockIdx.x * blockDim.x + threadIdx.x;
    int b = node >> 13;
    if (threadIdx.x < 32) {
        float s = g_part[b * 32 + threadIdx.x];
#pragma unroll
        for (int off = 16; off > 0; off >>= 1)
            s += __shfl_xor_sync(0xffffffffu, s, off);
        if (threadIdx.x == 0) ssum = s;
    }
    __syncthreads();
    float ss = ssum;
    float scale = (ss > 0.f) ? rsqrtf(ss) : 1.f;
    out[node] = g_absum[node] * scale;
}

// ---------------- launch ----------------
extern "C" void kernel_launch(void* const* d_in, const int* in_sizes, int n_in,
                              void* d_out, int out_size) {
    const float* q_embs    = (const float*)d_in[0];
    const float* emb       = (const float*)d_in[1];
    const int*   neighbors = (const int*)d_in[2];
    const int*   labels    = (const int*)d_in[3];
    const float* W1        = (const float*)d_in[4];
    const float* b1        = (const float*)d_in[5];
    const float* W2        = (const float*)d_in[6];
    const float* b2        = (const float*)d_in[7];
    const float* P1        = (const float*)d_in[8];
    const float* pb1       = (const float*)d_in[9];
    const float* P2        = (const float*)d_in[10];
    const float* pb2       = (const float*)d_in[11];
    float* out = (float*)d_out;

    cudaFuncSetAttribute(gemm_tc, cudaFuncAttributeMaxDynamicSharedMemorySize, SM_TOTAL);

    prep_wt<<<(WCOLS * D_) / 256, 256>>>(W1, P1);
    prep_qc<<<B_, 256>>>(q_embs, W1, b1, P1, pb1);
    prep_small<<<1, 1024>>>(W2, b2, P2, pb2);
    gemm_tc<<<(NODES / MTILE) * 2, 256, SM_TOTAL>>>(emb, labels);
    finalize_amps<<<NODES / 256, 256>>>();
    spmm_step1<<<NODES / 256, 256>>>(neighbors);
    spmm_step2<<<NODES / 256, 256>>>(neighbors);
    spmm_final<<<NODES / 256, 256>>>(neighbors);
    finalize<<<NODES / 256, 256>>>(out);
}